// round 9
// baseline (speedup 1.0000x reference)
#include <cuda_runtime.h>
#include <cstddef>
#include <cstdint>

// Problem dims (fixed)
#define B_   256
#define T_   512
#define IN_  128
#define H_   256
#define W1_  512
#define W2_  512
#define BT_  (B_ * T_)   // 131072

// ---------------------------------------------------------------------------
// Scratch (device globals — no allocations allowed anywhere)
// ---------------------------------------------------------------------------
__device__ float g_t1[(size_t)BT_ * W1_];   // Phase A layer1 out (reused as aw in Phase C)
__device__ float g_t2[(size_t)BT_ * W2_];   // Phase A layer2 out
__device__ float g_xin[(size_t)BT_ * H_];   // input-MLP output, layout [T, B, H]
__device__ float g_hs [(size_t)BT_ * H_];   // all hidden states,  layout [T, B, H]

// ---------------------------------------------------------------------------
// f32x2 packed helpers (Blackwell sm_100a)
// ---------------------------------------------------------------------------
typedef unsigned long long u64;

__device__ __forceinline__ u64 fma2(u64 a, u64 b, u64 c) {
    u64 d;
    asm("fma.rn.f32x2 %0, %1, %2, %3;" : "=l"(d) : "l"(a), "l"(b), "l"(c));
    return d;
}
__device__ __forceinline__ u64 dup2(float x) {
    u64 d; unsigned int u = __float_as_uint(x);
    asm("mov.b64 %0, {%1, %1};" : "=l"(d) : "r"(u));
    return d;
}
__device__ __forceinline__ void unpack2(u64 v, float& lo, float& hi) {
    unsigned int a, b;
    asm("mov.b64 {%0, %1}, %2;" : "=r"(a), "=r"(b) : "l"(v));
    lo = __uint_as_float(a); hi = __uint_as_float(b);
}

// ---------------------------------------------------------------------------
// mbarrier / bulk-async / cluster helpers
// ---------------------------------------------------------------------------
__device__ __forceinline__ uint32_t smem_u32(const void* p) {
    uint32_t a;
    asm("{ .reg .u64 t; cvta.to.shared.u64 t, %1; cvt.u32.u64 %0, t; }"
        : "=r"(a) : "l"(p));
    return a;
}
__device__ __forceinline__ void mbar_init(uint32_t mbar, uint32_t count) {
    asm volatile("mbarrier.init.shared.b64 [%0], %1;" :: "r"(mbar), "r"(count) : "memory");
}
__device__ __forceinline__ void mbar_expect_tx(uint32_t mbar, uint32_t bytes) {
    asm volatile("mbarrier.arrive.expect_tx.shared.b64 _, [%0], %1;"
                 :: "r"(mbar), "r"(bytes) : "memory");
}
__device__ __forceinline__ void mbar_wait_parity(uint32_t mbar, uint32_t parity) {
    asm volatile(
        "{\n\t"
        ".reg .pred P;\n\t"
        "WAIT_%=:\n\t"
        "mbarrier.try_wait.parity.shared.b64 P, [%0], %1, 0x989680;\n\t"
        "@P bra.uni DONE_%=;\n\t"
        "bra.uni WAIT_%=;\n\t"
        "DONE_%=:\n\t"
        "}"
        :: "r"(mbar), "r"(parity) : "memory");
}
__device__ __forceinline__ uint32_t mapa_rank(uint32_t addr, uint32_t rank) {
    uint32_t r;
    asm("mapa.shared::cluster.u32 %0, %1, %2;" : "=r"(r) : "r"(addr), "r"(rank));
    return r;
}
__device__ __forceinline__ void mbar_arrive_remote(uint32_t cluster_addr) {
    asm volatile("mbarrier.arrive.shared::cluster.b64 _, [%0];"
                 :: "r"(cluster_addr) : "memory");
}
// Multicast bulk copy: data + complete_tx delivered to the same smem offset /
// barrier offset in every CTA whose bit is set in mask.
__device__ __forceinline__ void bulk_g2s_mc(uint32_t dst_smem, const void* src_gmem,
                                            uint32_t bytes, uint32_t mbar, uint16_t mask) {
    asm volatile(
        "cp.async.bulk.shared::cluster.global.mbarrier::complete_tx::bytes.multicast::cluster "
        "[%0], [%1], %2, [%3], %4;"
        :: "r"(dst_smem), "l"(src_gmem), "r"(bytes), "r"(mbar), "h"(mask) : "memory");
}
__device__ __forceinline__ uint32_t cluster_rank() {
    uint32_t r; asm("mov.u32 %0, %%cluster_ctarank;" : "=r"(r)); return r;
}
#define CLUSTER_SYNC() do { \
    asm volatile("barrier.cluster.arrive.aligned;" ::: "memory"); \
    asm volatile("barrier.cluster.wait.aligned;"   ::: "memory"); \
} while (0)

// ---------------------------------------------------------------------------
// fp32 tiled GEMM with packed f32x2 compute (verified Rounds 5-8):
//   C[M,N] = act(A[M,K] @ W[K,N] + bias (+ Add))
// ---------------------------------------------------------------------------
template <int ACT, bool PERM, bool ADD>
__global__ void __launch_bounds__(256)
gemm_kernel(const float* __restrict__ A, const float* __restrict__ W,
            const float* __restrict__ bias, const float* __restrict__ Add,
            float* __restrict__ C, int M, int N, int K)
{
    constexpr int BM = 128, BN = 128, BK = 16, TM = 8, TN = 8;
    constexpr int THREADS = 256;
    __shared__ float As[BK][BM];
    __shared__ float Bs[BK][BN];

    const int tid  = threadIdx.x;
    const int bcol = blockIdx.x;
    const int brow = blockIdx.y;
    const int tx   = tid % (BN / TN);
    const int ty   = tid / (BN / TN);

    u64 acc2[TM][TN / 2];
#pragma unroll
    for (int i = 0; i < TM; i++)
#pragma unroll
        for (int j = 0; j < TN / 2; j++) acc2[i][j] = 0ull;

    const float* Ab = A + (size_t)brow * BM * K;
    const float* Wb = W + (size_t)bcol * BN;

    for (int k0 = 0; k0 < K; k0 += BK) {
#pragma unroll
        for (int i = tid * 4; i < BM * BK; i += THREADS * 4) {
            int r = i / BK, c = i % BK;
            float4 v = *(const float4*)(Ab + (size_t)r * K + k0 + c);
            As[c + 0][r] = v.x; As[c + 1][r] = v.y;
            As[c + 2][r] = v.z; As[c + 3][r] = v.w;
        }
#pragma unroll
        for (int i = tid * 4; i < BK * BN; i += THREADS * 4) {
            int r = i / BN, c = i % BN;
            float4 v = *(const float4*)(Wb + (size_t)(k0 + r) * N + c);
            *(float4*)&Bs[r][c] = v;
        }
        __syncthreads();

#pragma unroll
        for (int kk = 0; kk < BK; kk++) {
            ulonglong2 bb0 = *(const ulonglong2*)&Bs[kk][tx * TN];
            ulonglong2 bb1 = *(const ulonglong2*)&Bs[kk][tx * TN + 4];
            u64 bp[TN / 2] = { bb0.x, bb0.y, bb1.x, bb1.y };
            float4 a0 = *(const float4*)&As[kk][ty * TM];
            float4 a1 = *(const float4*)&As[kk][ty * TM + 4];
            u64 ad[TM];
            ad[0] = dup2(a0.x); ad[1] = dup2(a0.y);
            ad[2] = dup2(a0.z); ad[3] = dup2(a0.w);
            ad[4] = dup2(a1.x); ad[5] = dup2(a1.y);
            ad[6] = dup2(a1.z); ad[7] = dup2(a1.w);
#pragma unroll
            for (int i = 0; i < TM; i++)
#pragma unroll
                for (int j = 0; j < TN / 2; j++)
                    acc2[i][j] = fma2(ad[i], bp[j], acc2[i][j]);
        }
        __syncthreads();
    }

#pragma unroll
    for (int i = 0; i < TM; i++) {
        int row  = brow * BM + ty * TM + i;
        int orow = row;
        if (PERM) {
            int b = row / T_;
            int t = row - b * T_;
            orow = t * B_ + b;
        }
        float* Crow = C + (size_t)orow * N;
        const float* Arow = ADD ? (Add + (size_t)orow * N) : nullptr;
#pragma unroll
        for (int j = 0; j < TN / 2; j++) {
            int col = bcol * BN + tx * TN + j * 2;
            float v0, v1;
            unpack2(acc2[i][j], v0, v1);
            v0 += bias[col];
            v1 += bias[col + 1];
            if (ADD) { v0 += Arow[col]; v1 += Arow[col + 1]; }
            if (ACT == 1)      { v0 = fmaxf(v0, 0.f); v1 = fmaxf(v1, 0.f); }
            else if (ACT == 2) { v0 = tanhf(v0);      v1 = tanhf(v1);      }
            Crow[col]     = v0;
            Crow[col + 1] = v1;
        }
    }
}

// ---------------------------------------------------------------------------
// Phase B: persistent recurrence, 128 CTAs x 256 threads, clusters of 4.
// CTA c owns batch rows [2c, 2c+2). Weights streamed in 32KB chunks via
// MULTICAST cp.async.bulk, rank s produces stage s (NSTAGE=4).
// WARP-AUTONOMOUS consumption (no per-chunk CTA barrier):
//   full[s] : per-CTA, count 1 + tx; re-armed by warp 0 lane 0 post-consume.
//   empty[s]: on rank s, count 32 (8 warps x 4 CTAs); lane 0 of EACH warp
//             remote-arrives after that warp finishes the chunk.
// Warps skew freely, bounded by the 4-stage ring. Layer-boundary
// __syncthreads (3/step) still protect activation tiles.
// Chunk schedule per step (64 chunks x 8192 floats):
//   chunks  0..15 : W1 rows [16j,16j+16) x 512
//   chunks 16..47 : W2 rows [16j,16j+16) x 512
//   chunks 48..63 : W3 rows [32j,32j+32) x 256
// ---------------------------------------------------------------------------
#define NSTAGE      4
#define CHUNK_F     8192
#define CHUNK_BYTES (CHUNK_F * 4)
#define CHUNKS_PER_STEP 64
#define TOTAL_CHUNKS    (T_ * CHUNKS_PER_STEP)
#define MC_MASK     0xFu
#define EMPTY_ARRIVALS 32    // 8 warps x 4 CTAs

// dynamic smem layout (floats)
#define SM_WBUF  0
#define SM_HT    (NSTAGE * CHUNK_F)          // 512  (H_ * 2)
#define SM_Y1T   (SM_HT + H_ * 2)            // 1024 (W1_ * 2)
#define SM_Y2T   (SM_Y1T + W1_ * 2)          // 1024
#define SM_B1    (SM_Y2T + W2_ * 2)          // 512
#define SM_B2    (SM_B1 + W1_)               // 512
#define SM_B3    (SM_B2 + W2_)               // 256
#define SM_FULL  (SM_B3 + H_)                // 4 mbarriers (2 floats each)
#define SM_EMPTY (SM_FULL + 2 * NSTAGE)
#define SMEM_FLOATS (SM_EMPTY + 2 * NSTAGE)
#define SMEM_BYTES  (SMEM_FLOATS * 4)

struct WSrc { const float* w1; const float* w2; const float* w3; };

__device__ __forceinline__ const float* chunk_src(const WSrc& w, int cg) {
    int c = cg & (CHUNKS_PER_STEP - 1);
    if (c < 16)      return w.w1 + (size_t)c * 16 * W1_;
    else if (c < 48) return w.w2 + (size_t)(c - 16) * 16 * W2_;
    else             return w.w3 + (size_t)(c - 48) * 32 * H_;
}

__global__ void __launch_bounds__(256, 1) __cluster_dims__(4, 1, 1)
recurrence_kernel(const float* __restrict__ w1, const float* __restrict__ b1,
                  const float* __restrict__ w2, const float* __restrict__ b2,
                  const float* __restrict__ w3, const float* __restrict__ b3,
                  const float* __restrict__ xin, float* __restrict__ hs)
{
    extern __shared__ float smem[];
    float* wbuf = smem + SM_WBUF;
    float* hT   = smem + SM_HT;    // act transposed: [k][m], m = 0..1
    float* y1T  = smem + SM_Y1T;
    float* y2T  = smem + SM_Y2T;
    float* bs1  = smem + SM_B1;
    float* bs2  = smem + SM_B2;
    float* bs3  = smem + SM_B3;
    const uint32_t fullb  = smem_u32(smem + SM_FULL);
    const uint32_t emptyb = smem_u32(smem + SM_EMPTY);

    const int tid  = threadIdx.x;
    const int lane = tid & 31;
    const int wid  = tid >> 5;
    const int b0   = blockIdx.x * 2;    // first batch row of this CTA
    const uint32_t rank = cluster_rank();
    WSrc wsrc = { w1, w2, w3 };

    for (int i = tid; i < W1_; i += 256) bs1[i] = b1[i];
    for (int i = tid; i < W2_; i += 256) bs2[i] = b2[i];
    for (int i = tid; i < H_;  i += 256) bs3[i] = b3[i];
    for (int i = tid; i < H_ * 2; i += 256) hT[i] = 0.f;
    if (tid == 0) {
#pragma unroll
        for (int s = 0; s < NSTAGE; s++) {
            mbar_init(fullb  + s * 8, 1);
            mbar_init(emptyb + s * 8, EMPTY_ARRIVALS);
        }
    }
    __syncthreads();

    // prologue: arm all full barriers, cluster-sync, each rank produces its stage
    if (tid == 0) {
#pragma unroll
        for (int s = 0; s < NSTAGE; s++) mbar_expect_tx(fullb + s * 8, CHUNK_BYTES);
    }
    CLUSTER_SYNC();
    if (tid == 0) {
        bulk_g2s_mc(smem_u32(wbuf + rank * CHUNK_F), chunk_src(wsrc, (int)rank),
                    CHUNK_BYTES, fullb + rank * 8, MC_MASK);
    }

    int chunk = 0;   // per-warp consumer position (uniform within a warp)

    // Per-warp bookkeeping after this warp finishes reading `chunk` (stage s):
    //   warp0 lane0: re-arm local full for the stage's next use (phase-correct:
    //   this warp observed the flip; out-of-order complete_tx is legal).
    //   lane0 of every warp: remote-arrive on producer's empty[s].
    //   warp0 lane0 of producer rank: wait all 32 arrivals of this use, refill.
#define CHUNK_BOOKKEEP()                                                        \
    do {                                                                        \
        if (lane == 0 && chunk + NSTAGE < TOTAL_CHUNKS) {                       \
            const int s_ = chunk & (NSTAGE - 1);                                \
            if (wid == 0) mbar_expect_tx(fullb + s_ * 8, CHUNK_BYTES);          \
            mbar_arrive_remote(mapa_rank(emptyb + s_ * 8, (uint32_t)s_));       \
            if (wid == 0 && rank == (uint32_t)s_) {                             \
                mbar_wait_parity(emptyb + s_ * 8, (chunk >> 2) & 1);            \
                bulk_g2s_mc(smem_u32(wbuf + s_ * CHUNK_F),                      \
                            chunk_src(wsrc, chunk + NSTAGE),                    \
                            CHUNK_BYTES, fullb + s_ * 8, MC_MASK);              \
            }                                                                   \
        }                                                                       \
        chunk++;                                                                \
    } while (0)

    for (int t = 0; t < T_; t++) {
        const int c0 = tid * 2;

        // ===== Layer 1: y1 = relu(h @ W1 + b1), K=256 (16 chunks x 16k) =====
        {
            u64 a0 = 0, a1 = 0;
            for (int j = 0; j < 16; j++) {
                const int s = chunk & (NSTAGE - 1);
                mbar_wait_parity(fullb + s * 8, (chunk >> 2) & 1);
                const float* wb = wbuf + s * CHUNK_F;
#pragma unroll
                for (int kk = 0; kk < 16; kk++) {
                    const int k = j * 16 + kk;
                    u64 r = *(const u64*)(hT + k * 2);           // broadcast
                    float2 w = *(const float2*)(wb + kk * W1_ + c0);
                    a0 = fma2(r, dup2(w.x), a0);
                    a1 = fma2(r, dup2(w.y), a1);
                }
                CHUNK_BOOKKEEP();
            }
            float v0, v1;
            const float bb0 = bs1[c0], bb1 = bs1[c0 + 1];
            unpack2(a0, v0, v1);
            *(float2*)(y1T + c0 * 2) =
                make_float2(fmaxf(v0 + bb0, 0.f), fmaxf(v1 + bb0, 0.f));
            unpack2(a1, v0, v1);
            *(float2*)(y1T + (c0 + 1) * 2) =
                make_float2(fmaxf(v0 + bb1, 0.f), fmaxf(v1 + bb1, 0.f));
        }
        __syncthreads();

        // ===== Layer 2: y2 = relu(y1 @ W2 + b2), K=512 (32 chunks x 16k) ====
        {
            u64 a0 = 0, a1 = 0;
            for (int j = 0; j < 32; j++) {
                const int s = chunk & (NSTAGE - 1);
                mbar_wait_parity(fullb + s * 8, (chunk >> 2) & 1);
                const float* wb = wbuf + s * CHUNK_F;
#pragma unroll
                for (int kk = 0; kk < 16; kk++) {
                    const int k = j * 16 + kk;
                    u64 r = *(const u64*)(y1T + k * 2);
                    float2 w = *(const float2*)(wb + kk * W2_ + c0);
                    a0 = fma2(r, dup2(w.x), a0);
                    a1 = fma2(r, dup2(w.y), a1);
                }
                CHUNK_BOOKKEEP();
            }
            float v0, v1;
            const float bb0 = bs2[c0], bb1 = bs2[c0 + 1];
            unpack2(a0, v0, v1);
            *(float2*)(y2T + c0 * 2) =
                make_float2(fmaxf(v0 + bb0, 0.f), fmaxf(v1 + bb0, 0.f));
            unpack2(a1, v0, v1);
            *(float2*)(y2T + (c0 + 1) * 2) =
                make_float2(fmaxf(v0 + bb1, 0.f), fmaxf(v1 + bb1, 0.f));
        }
        __syncthreads();

        // ===== Layer 3: h = tanh(y2 @ W3 + b3 + xin_t), K=512 (16 x 32k) ====
        {
            const int c = tid;   // one column per thread (N=256)
            u64 ae = 0, ao = 0;  // even/odd split for ILP
            for (int j = 0; j < 16; j++) {
                const int s = chunk & (NSTAGE - 1);
                mbar_wait_parity(fullb + s * 8, (chunk >> 2) & 1);
                const float* wb = wbuf + s * CHUNK_F;
#pragma unroll
                for (int kk = 0; kk < 32; kk += 2) {
                    const int k = j * 32 + kk;
                    u64 r0 = *(const u64*)(y2T + k * 2);
                    u64 r1 = *(const u64*)(y2T + (k + 1) * 2);
                    ae = fma2(r0, dup2(wb[kk * H_ + c]),       ae);
                    ao = fma2(r1, dup2(wb[(kk + 1) * H_ + c]), ao);
                }
                CHUNK_BOOKKEEP();
            }
            float e0, e1, o0, o1;
            unpack2(ae, e0, e1); unpack2(ao, o0, o1);
            const float bb = bs3[c];
            const float* xr = xin + (size_t)t * B_ * H_ + (size_t)b0 * H_ + c;
            float*       hr = hs  + (size_t)t * B_ * H_ + (size_t)b0 * H_ + c;
            float v0 = tanhf(e0 + o0 + bb + xr[0 * H_]);
            float v1 = tanhf(e1 + o1 + bb + xr[1 * H_]);
            hr[0 * H_] = v0; hr[1 * H_] = v1;
            *(float2*)(hT + c * 2) = make_float2(v0, v1);
        }
        __syncthreads();    // hT ready before next step's layer 1
    }

    CLUSTER_SYNC();          // no CTA exits while peers' multicasts may target it
#undef CHUNK_BOOKKEEP
}

// ---------------------------------------------------------------------------
// Phase C reduction: online softmax over T (axis 0) + weighted sum of hs.
// ---------------------------------------------------------------------------
__global__ void attn_reduce_kernel(const float* __restrict__ aw,
                                   const float* __restrict__ hs,
                                   float* __restrict__ out)
{
    const int b = blockIdx.x;
    const int h = threadIdx.x;
    float m = -1e30f, s = 0.f, acc = 0.f;
    for (int t = 0; t < T_; t++) {
        size_t idx = ((size_t)t * B_ + b) * H_ + h;
        float a  = aw[idx];
        float hv = hs[idx];
        if (a > m) {
            float c = __expf(m - a);
            s   = s * c + 1.f;
            acc = acc * c + hv;
            m   = a;
        } else {
            float e = __expf(a - m);
            s   += e;
            acc += e * hv;
        }
    }
    out[(size_t)b * H_ + h] = acc / s;
}

// ---------------------------------------------------------------------------
// Launch
// ---------------------------------------------------------------------------
extern "C" void kernel_launch(void* const* d_in, const int* in_sizes, int n_in,
                              void* d_out, int out_size)
{
    const float* x     = (const float*)d_in[0];
    const float* h_w1  = (const float*)d_in[1];
    const float* h_b1  = (const float*)d_in[2];
    const float* h_w2  = (const float*)d_in[3];
    const float* h_b2  = (const float*)d_in[4];
    const float* h_w3  = (const float*)d_in[5];
    const float* h_b3  = (const float*)d_in[6];
    const float* i_w1  = (const float*)d_in[7];
    const float* i_b1  = (const float*)d_in[8];
    const float* i_w2  = (const float*)d_in[9];
    const float* i_b2  = (const float*)d_in[10];
    const float* i_w3  = (const float*)d_in[11];
    const float* i_b3  = (const float*)d_in[12];
    const float* att_w = (const float*)d_in[13];
    const float* att_b = (const float*)d_in[14];
    float* out = (float*)d_out;

    float *t1, *t2, *xin, *hs;
    cudaGetSymbolAddress((void**)&t1,  g_t1);
    cudaGetSymbolAddress((void**)&t2,  g_t2);
    cudaGetSymbolAddress((void**)&xin, g_xin);
    cudaGetSymbolAddress((void**)&hs,  g_hs);
    float* aw = t1;   // reuse t1 for attention logits in Phase C

    // ---------------- Phase A: input MLP over all B*T rows ----------------
    gemm_kernel<1,false,false><<<dim3(W1_/128, BT_/128), 256>>>(
        x,  i_w1, i_b1, nullptr, t1,  BT_, W1_, IN_);
    gemm_kernel<1,false,false><<<dim3(W2_/128, BT_/128), 256>>>(
        t1, i_w2, i_b2, nullptr, t2,  BT_, W2_, W1_);
    gemm_kernel<0,true ,false><<<dim3(H_/128, BT_/128), 256>>>(
        t2, i_w3, i_b3, nullptr, xin, BT_, H_, W2_);

    // ---------------- Phase B: persistent recurrence (ONE launch) ---------
    cudaFuncSetAttribute(recurrence_kernel,
                         cudaFuncAttributeMaxDynamicSharedMemorySize, SMEM_BYTES);
    recurrence_kernel<<<128, 256, SMEM_BYTES>>>(
        h_w1, h_b1, h_w2, h_b2, h_w3, h_b3, xin, hs);

    // ---------------- Phase C: attention pooling --------------------------
    gemm_kernel<2,false,false><<<dim3(H_/128, BT_/128), 256>>>(
        hs, att_w, att_b, nullptr, aw, BT_, H_, H_);
    attn_reduce_kernel<<<B_, H_>>>(aw, hs, out);
}

// round 10
// speedup vs baseline: 1.2652x; 1.2652x over previous
#include <cuda_runtime.h>
#include <cstddef>
#include <cstdint>

// Problem dims (fixed)
#define B_   256
#define T_   512
#define IN_  128
#define H_   256
#define W1_  512
#define W2_  512
#define BT_  (B_ * T_)   // 131072

// ---------------------------------------------------------------------------
// Scratch (device globals — no allocations allowed anywhere)
// ---------------------------------------------------------------------------
__device__ float g_t1[(size_t)BT_ * W1_];   // Phase A layer1 out (reused as aw in Phase C)
__device__ float g_t2[(size_t)BT_ * W2_];   // Phase A layer2 out
__device__ float g_xin[(size_t)BT_ * H_];   // input-MLP output, layout [T, B, H]
__device__ float g_hs [(size_t)BT_ * H_];   // all hidden states,  layout [T, B, H]

// ---------------------------------------------------------------------------
// f32x2 packed helpers (Blackwell sm_100a)
// ---------------------------------------------------------------------------
typedef unsigned long long u64;

__device__ __forceinline__ u64 fma2(u64 a, u64 b, u64 c) {
    u64 d;
    asm("fma.rn.f32x2 %0, %1, %2, %3;" : "=l"(d) : "l"(a), "l"(b), "l"(c));
    return d;
}
__device__ __forceinline__ u64 dup2(float x) {
    u64 d; unsigned int u = __float_as_uint(x);
    asm("mov.b64 %0, {%1, %1};" : "=l"(d) : "r"(u));
    return d;
}
__device__ __forceinline__ void unpack2(u64 v, float& lo, float& hi) {
    unsigned int a, b;
    asm("mov.b64 {%0, %1}, %2;" : "=r"(a), "=r"(b) : "l"(v));
    lo = __uint_as_float(a); hi = __uint_as_float(b);
}

// ---------------------------------------------------------------------------
// mbarrier / bulk-async / cluster helpers
// ---------------------------------------------------------------------------
__device__ __forceinline__ uint32_t smem_u32(const void* p) {
    uint32_t a;
    asm("{ .reg .u64 t; cvta.to.shared.u64 t, %1; cvt.u32.u64 %0, t; }"
        : "=r"(a) : "l"(p));
    return a;
}
__device__ __forceinline__ void mbar_init(uint32_t mbar, uint32_t count) {
    asm volatile("mbarrier.init.shared.b64 [%0], %1;" :: "r"(mbar), "r"(count) : "memory");
}
__device__ __forceinline__ void mbar_expect_tx(uint32_t mbar, uint32_t bytes) {
    asm volatile("mbarrier.arrive.expect_tx.shared.b64 _, [%0], %1;"
                 :: "r"(mbar), "r"(bytes) : "memory");
}
__device__ __forceinline__ void mbar_wait_parity(uint32_t mbar, uint32_t parity) {
    asm volatile(
        "{\n\t"
        ".reg .pred P;\n\t"
        "WAIT_%=:\n\t"
        "mbarrier.try_wait.parity.shared.b64 P, [%0], %1, 0x989680;\n\t"
        "@P bra.uni DONE_%=;\n\t"
        "bra.uni WAIT_%=;\n\t"
        "DONE_%=:\n\t"
        "}"
        :: "r"(mbar), "r"(parity) : "memory");
}
__device__ __forceinline__ uint32_t mapa_rank(uint32_t addr, uint32_t rank) {
    uint32_t r;
    asm("mapa.shared::cluster.u32 %0, %1, %2;" : "=r"(r) : "r"(addr), "r"(rank));
    return r;
}
__device__ __forceinline__ void mbar_arrive_remote(uint32_t cluster_addr) {
    asm volatile("mbarrier.arrive.shared::cluster.b64 _, [%0];"
                 :: "r"(cluster_addr) : "memory");
}
// Multicast bulk copy: data + complete_tx delivered to the same smem offset /
// barrier offset in every CTA whose bit is set in mask.
__device__ __forceinline__ void bulk_g2s_mc(uint32_t dst_smem, const void* src_gmem,
                                            uint32_t bytes, uint32_t mbar, uint16_t mask) {
    asm volatile(
        "cp.async.bulk.shared::cluster.global.mbarrier::complete_tx::bytes.multicast::cluster "
        "[%0], [%1], %2, [%3], %4;"
        :: "r"(dst_smem), "l"(src_gmem), "r"(bytes), "r"(mbar), "h"(mask) : "memory");
}
__device__ __forceinline__ uint32_t cluster_rank() {
    uint32_t r; asm("mov.u32 %0, %%cluster_ctarank;" : "=r"(r)); return r;
}
#define CLUSTER_SYNC() do { \
    asm volatile("barrier.cluster.arrive.aligned;" ::: "memory"); \
    asm volatile("barrier.cluster.wait.aligned;"   ::: "memory"); \
} while (0)

// ---------------------------------------------------------------------------
// fp32 tiled GEMM with packed f32x2 compute (verified Rounds 5-8):
//   C[M,N] = act(A[M,K] @ W[K,N] + bias (+ Add))
// ---------------------------------------------------------------------------
template <int ACT, bool PERM, bool ADD>
__global__ void __launch_bounds__(256)
gemm_kernel(const float* __restrict__ A, const float* __restrict__ W,
            const float* __restrict__ bias, const float* __restrict__ Add,
            float* __restrict__ C, int M, int N, int K)
{
    constexpr int BM = 128, BN = 128, BK = 16, TM = 8, TN = 8;
    constexpr int THREADS = 256;
    __shared__ float As[BK][BM];
    __shared__ float Bs[BK][BN];

    const int tid  = threadIdx.x;
    const int bcol = blockIdx.x;
    const int brow = blockIdx.y;
    const int tx   = tid % (BN / TN);
    const int ty   = tid / (BN / TN);

    u64 acc2[TM][TN / 2];
#pragma unroll
    for (int i = 0; i < TM; i++)
#pragma unroll
        for (int j = 0; j < TN / 2; j++) acc2[i][j] = 0ull;

    const float* Ab = A + (size_t)brow * BM * K;
    const float* Wb = W + (size_t)bcol * BN;

    for (int k0 = 0; k0 < K; k0 += BK) {
#pragma unroll
        for (int i = tid * 4; i < BM * BK; i += THREADS * 4) {
            int r = i / BK, c = i % BK;
            float4 v = *(const float4*)(Ab + (size_t)r * K + k0 + c);
            As[c + 0][r] = v.x; As[c + 1][r] = v.y;
            As[c + 2][r] = v.z; As[c + 3][r] = v.w;
        }
#pragma unroll
        for (int i = tid * 4; i < BK * BN; i += THREADS * 4) {
            int r = i / BN, c = i % BN;
            float4 v = *(const float4*)(Wb + (size_t)(k0 + r) * N + c);
            *(float4*)&Bs[r][c] = v;
        }
        __syncthreads();

#pragma unroll
        for (int kk = 0; kk < BK; kk++) {
            ulonglong2 bb0 = *(const ulonglong2*)&Bs[kk][tx * TN];
            ulonglong2 bb1 = *(const ulonglong2*)&Bs[kk][tx * TN + 4];
            u64 bp[TN / 2] = { bb0.x, bb0.y, bb1.x, bb1.y };
            float4 a0 = *(const float4*)&As[kk][ty * TM];
            float4 a1 = *(const float4*)&As[kk][ty * TM + 4];
            u64 ad[TM];
            ad[0] = dup2(a0.x); ad[1] = dup2(a0.y);
            ad[2] = dup2(a0.z); ad[3] = dup2(a0.w);
            ad[4] = dup2(a1.x); ad[5] = dup2(a1.y);
            ad[6] = dup2(a1.z); ad[7] = dup2(a1.w);
#pragma unroll
            for (int i = 0; i < TM; i++)
#pragma unroll
                for (int j = 0; j < TN / 2; j++)
                    acc2[i][j] = fma2(ad[i], bp[j], acc2[i][j]);
        }
        __syncthreads();
    }

#pragma unroll
    for (int i = 0; i < TM; i++) {
        int row  = brow * BM + ty * TM + i;
        int orow = row;
        if (PERM) {
            int b = row / T_;
            int t = row - b * T_;
            orow = t * B_ + b;
        }
        float* Crow = C + (size_t)orow * N;
        const float* Arow = ADD ? (Add + (size_t)orow * N) : nullptr;
#pragma unroll
        for (int j = 0; j < TN / 2; j++) {
            int col = bcol * BN + tx * TN + j * 2;
            float v0, v1;
            unpack2(acc2[i][j], v0, v1);
            v0 += bias[col];
            v1 += bias[col + 1];
            if (ADD) { v0 += Arow[col]; v1 += Arow[col + 1]; }
            if (ACT == 1)      { v0 = fmaxf(v0, 0.f); v1 = fmaxf(v1, 0.f); }
            else if (ACT == 2) { v0 = tanhf(v0);      v1 = tanhf(v1);      }
            Crow[col]     = v0;
            Crow[col + 1] = v1;
        }
    }
}

// ---------------------------------------------------------------------------
// Phase B: persistent recurrence, 128 CTAs x 256 threads, clusters of 4.
// CTA c owns batch rows [2c, 2c+2). R8 protocol (verified 16.75ms) with ONE
// change: chunks consumed in PAIRS — one __syncthreads + one bookkeep per
// 64KB instead of per 32KB (32 boundaries/step instead of 64).
//   full[s] : per-CTA, count 1 + tx; re-armed by tid0 post-pair.
//   empty[s]: on rank s, count 4; tid0 of each CTA remote-arrives post-pair.
// Chunk schedule per step (64 chunks x 8192 floats):
//   chunks  0..15 : W1 rows [16j,16j+16) x 512
//   chunks 16..47 : W2 rows [16j,16j+16) x 512
//   chunks 48..63 : W3 rows [32j,32j+32) x 256
// ---------------------------------------------------------------------------
#define NSTAGE      4
#define CHUNK_F     8192
#define CHUNK_BYTES (CHUNK_F * 4)
#define CHUNKS_PER_STEP 64
#define TOTAL_CHUNKS    (T_ * CHUNKS_PER_STEP)
#define MC_MASK     0xFu

// dynamic smem layout (floats)
#define SM_WBUF  0
#define SM_HT    (NSTAGE * CHUNK_F)          // 512  (H_ * 2)
#define SM_Y1T   (SM_HT + H_ * 2)            // 1024 (W1_ * 2)
#define SM_Y2T   (SM_Y1T + W1_ * 2)          // 1024
#define SM_B1    (SM_Y2T + W2_ * 2)          // 512
#define SM_B2    (SM_B1 + W1_)               // 512
#define SM_B3    (SM_B2 + W2_)               // 256
#define SM_FULL  (SM_B3 + H_)                // 4 mbarriers (2 floats each)
#define SM_EMPTY (SM_FULL + 2 * NSTAGE)
#define SMEM_FLOATS (SM_EMPTY + 2 * NSTAGE)
#define SMEM_BYTES  (SMEM_FLOATS * 4)

struct WSrc { const float* w1; const float* w2; const float* w3; };

__device__ __forceinline__ const float* chunk_src(const WSrc& w, int cg) {
    int c = cg & (CHUNKS_PER_STEP - 1);
    if (c < 16)      return w.w1 + (size_t)c * 16 * W1_;
    else if (c < 48) return w.w2 + (size_t)(c - 16) * 16 * W2_;
    else             return w.w3 + (size_t)(c - 48) * 32 * H_;
}

__global__ void __launch_bounds__(256, 1) __cluster_dims__(4, 1, 1)
recurrence_kernel(const float* __restrict__ w1, const float* __restrict__ b1,
                  const float* __restrict__ w2, const float* __restrict__ b2,
                  const float* __restrict__ w3, const float* __restrict__ b3,
                  const float* __restrict__ xin, float* __restrict__ hs)
{
    extern __shared__ float smem[];
    float* wbuf = smem + SM_WBUF;
    float* hT   = smem + SM_HT;    // act transposed: [k][m], m = 0..1
    float* y1T  = smem + SM_Y1T;
    float* y2T  = smem + SM_Y2T;
    float* bs1  = smem + SM_B1;
    float* bs2  = smem + SM_B2;
    float* bs3  = smem + SM_B3;
    const uint32_t fullb  = smem_u32(smem + SM_FULL);
    const uint32_t emptyb = smem_u32(smem + SM_EMPTY);

    const int tid = threadIdx.x;
    const int b0  = blockIdx.x * 2;    // first batch row of this CTA
    const uint32_t rank = cluster_rank();
    WSrc wsrc = { w1, w2, w3 };

    for (int i = tid; i < W1_; i += 256) bs1[i] = b1[i];
    for (int i = tid; i < W2_; i += 256) bs2[i] = b2[i];
    for (int i = tid; i < H_;  i += 256) bs3[i] = b3[i];
    for (int i = tid; i < H_ * 2; i += 256) hT[i] = 0.f;
    if (tid == 0) {
#pragma unroll
        for (int s = 0; s < NSTAGE; s++) {
            mbar_init(fullb  + s * 8, 1);
            mbar_init(emptyb + s * 8, NSTAGE);   // 4 consumer arrivals
        }
    }
    __syncthreads();

    // prologue: arm all full barriers, cluster-sync, each rank produces its stage
    if (tid == 0) {
#pragma unroll
        for (int s = 0; s < NSTAGE; s++) mbar_expect_tx(fullb + s * 8, CHUNK_BYTES);
    }
    CLUSTER_SYNC();
    if (tid == 0) {
        bulk_g2s_mc(smem_u32(wbuf + rank * CHUNK_F), chunk_src(wsrc, (int)rank),
                    CHUNK_BYTES, fullb + rank * 8, MC_MASK);
    }

    int chunk = 0;   // uniform consumer position (always even at pair start)

    // Pair bookkeeping after consuming chunks {chunk, chunk+1}: one CTA
    // barrier, then tid0 re-arms fulls, signals empties, producers refill.
#define PAIR_BOOKKEEP()                                                         \
    do {                                                                        \
        __syncthreads();                                                        \
        if (tid == 0) {                                                         \
            _Pragma("unroll")                                                   \
            for (int q = 0; q < 2; q++) {                                       \
                const int cq = chunk + q;                                       \
                if (cq + NSTAGE < TOTAL_CHUNKS) {                               \
                    const int s_ = cq & (NSTAGE - 1);                           \
                    mbar_expect_tx(fullb + s_ * 8, CHUNK_BYTES);                \
                    mbar_arrive_remote(mapa_rank(emptyb + s_ * 8, (uint32_t)s_));\
                    if (rank == (uint32_t)s_) {                                 \
                        mbar_wait_parity(emptyb + s_ * 8, (cq >> 2) & 1);       \
                        bulk_g2s_mc(smem_u32(wbuf + s_ * CHUNK_F),              \
                                    chunk_src(wsrc, cq + NSTAGE),               \
                                    CHUNK_BYTES, fullb + s_ * 8, MC_MASK);      \
                    }                                                           \
                }                                                               \
            }                                                                   \
        }                                                                       \
        chunk += 2;                                                             \
    } while (0)

    for (int t = 0; t < T_; t++) {
        const int c0 = tid * 2;

        // ===== Layer 1: y1 = relu(h @ W1 + b1), K=256 (8 pairs x 32k) =======
        {
            u64 a0 = 0, a1 = 0;
            for (int jp = 0; jp < 8; jp++) {
                const int s0 = chunk & (NSTAGE - 1);
                const int s1 = (chunk + 1) & (NSTAGE - 1);
                mbar_wait_parity(fullb + s0 * 8, (chunk >> 2) & 1);
                mbar_wait_parity(fullb + s1 * 8, ((chunk + 1) >> 2) & 1);
                const float* wb0 = wbuf + s0 * CHUNK_F;
                const float* wb1 = wbuf + s1 * CHUNK_F;
#pragma unroll
                for (int kk = 0; kk < 16; kk++) {
                    const int k = jp * 32 + kk;
                    u64 r = *(const u64*)(hT + k * 2);           // broadcast
                    float2 w = *(const float2*)(wb0 + kk * W1_ + c0);
                    a0 = fma2(r, dup2(w.x), a0);
                    a1 = fma2(r, dup2(w.y), a1);
                }
#pragma unroll
                for (int kk = 0; kk < 16; kk++) {
                    const int k = jp * 32 + 16 + kk;
                    u64 r = *(const u64*)(hT + k * 2);
                    float2 w = *(const float2*)(wb1 + kk * W1_ + c0);
                    a0 = fma2(r, dup2(w.x), a0);
                    a1 = fma2(r, dup2(w.y), a1);
                }
                PAIR_BOOKKEEP();
            }
            float v0, v1;
            const float bb0 = bs1[c0], bb1 = bs1[c0 + 1];
            unpack2(a0, v0, v1);
            *(float2*)(y1T + c0 * 2) =
                make_float2(fmaxf(v0 + bb0, 0.f), fmaxf(v1 + bb0, 0.f));
            unpack2(a1, v0, v1);
            *(float2*)(y1T + (c0 + 1) * 2) =
                make_float2(fmaxf(v0 + bb1, 0.f), fmaxf(v1 + bb1, 0.f));
        }
        __syncthreads();

        // ===== Layer 2: y2 = relu(y1 @ W2 + b2), K=512 (16 pairs x 32k) =====
        {
            u64 a0 = 0, a1 = 0;
            for (int jp = 0; jp < 16; jp++) {
                const int s0 = chunk & (NSTAGE - 1);
                const int s1 = (chunk + 1) & (NSTAGE - 1);
                mbar_wait_parity(fullb + s0 * 8, (chunk >> 2) & 1);
                mbar_wait_parity(fullb + s1 * 8, ((chunk + 1) >> 2) & 1);
                const float* wb0 = wbuf + s0 * CHUNK_F;
                const float* wb1 = wbuf + s1 * CHUNK_F;
#pragma unroll
                for (int kk = 0; kk < 16; kk++) {
                    const int k = jp * 32 + kk;
                    u64 r = *(const u64*)(y1T + k * 2);
                    float2 w = *(const float2*)(wb0 + kk * W2_ + c0);
                    a0 = fma2(r, dup2(w.x), a0);
                    a1 = fma2(r, dup2(w.y), a1);
                }
#pragma unroll
                for (int kk = 0; kk < 16; kk++) {
                    const int k = jp * 32 + 16 + kk;
                    u64 r = *(const u64*)(y1T + k * 2);
                    float2 w = *(const float2*)(wb1 + kk * W2_ + c0);
                    a0 = fma2(r, dup2(w.x), a0);
                    a1 = fma2(r, dup2(w.y), a1);
                }
                PAIR_BOOKKEEP();
            }
            float v0, v1;
            const float bb0 = bs2[c0], bb1 = bs2[c0 + 1];
            unpack2(a0, v0, v1);
            *(float2*)(y2T + c0 * 2) =
                make_float2(fmaxf(v0 + bb0, 0.f), fmaxf(v1 + bb0, 0.f));
            unpack2(a1, v0, v1);
            *(float2*)(y2T + (c0 + 1) * 2) =
                make_float2(fmaxf(v0 + bb1, 0.f), fmaxf(v1 + bb1, 0.f));
        }
        __syncthreads();

        // ===== Layer 3: h = tanh(y2 @ W3 + b3 + xin_t), K=512 (8 pairs x 64k)
        {
            const int c = tid;   // one column per thread (N=256)
            u64 ae = 0, ao = 0;  // even/odd split for ILP
            for (int jp = 0; jp < 8; jp++) {
                const int s0 = chunk & (NSTAGE - 1);
                const int s1 = (chunk + 1) & (NSTAGE - 1);
                mbar_wait_parity(fullb + s0 * 8, (chunk >> 2) & 1);
                mbar_wait_parity(fullb + s1 * 8, ((chunk + 1) >> 2) & 1);
                const float* wb0 = wbuf + s0 * CHUNK_F;
                const float* wb1 = wbuf + s1 * CHUNK_F;
#pragma unroll
                for (int kk = 0; kk < 32; kk += 2) {
                    const int k = jp * 64 + kk;
                    u64 r0 = *(const u64*)(y2T + k * 2);
                    u64 r1 = *(const u64*)(y2T + (k + 1) * 2);
                    ae = fma2(r0, dup2(wb0[kk * H_ + c]),       ae);
                    ao = fma2(r1, dup2(wb0[(kk + 1) * H_ + c]), ao);
                }
#pragma unroll
                for (int kk = 0; kk < 32; kk += 2) {
                    const int k = jp * 64 + 32 + kk;
                    u64 r0 = *(const u64*)(y2T + k * 2);
                    u64 r1 = *(const u64*)(y2T + (k + 1) * 2);
                    ae = fma2(r0, dup2(wb1[kk * H_ + c]),       ae);
                    ao = fma2(r1, dup2(wb1[(kk + 1) * H_ + c]), ao);
                }
                PAIR_BOOKKEEP();
            }
            float e0, e1, o0, o1;
            unpack2(ae, e0, e1); unpack2(ao, o0, o1);
            const float bb = bs3[c];
            const float* xr = xin + (size_t)t * B_ * H_ + (size_t)b0 * H_ + c;
            float*       hr = hs  + (size_t)t * B_ * H_ + (size_t)b0 * H_ + c;
            float v0 = tanhf(e0 + o0 + bb + xr[0 * H_]);
            float v1 = tanhf(e1 + o1 + bb + xr[1 * H_]);
            hr[0 * H_] = v0; hr[1 * H_] = v1;
            *(float2*)(hT + c * 2) = make_float2(v0, v1);
        }
        __syncthreads();    // hT ready before next step's layer 1
    }

    CLUSTER_SYNC();          // no CTA exits while peers' multicasts may target it
#undef PAIR_BOOKKEEP
}

// ---------------------------------------------------------------------------
// Phase C reduction: online softmax over T (axis 0) + weighted sum of hs.
// ---------------------------------------------------------------------------
__global__ void attn_reduce_kernel(const float* __restrict__ aw,
                                   const float* __restrict__ hs,
                                   float* __restrict__ out)
{
    const int b = blockIdx.x;
    const int h = threadIdx.x;
    float m = -1e30f, s = 0.f, acc = 0.f;
    for (int t = 0; t < T_; t++) {
        size_t idx = ((size_t)t * B_ + b) * H_ + h;
        float a  = aw[idx];
        float hv = hs[idx];
        if (a > m) {
            float c = __expf(m - a);
            s   = s * c + 1.f;
            acc = acc * c + hv;
            m   = a;
        } else {
            float e = __expf(a - m);
            s   += e;
            acc += e * hv;
        }
    }
    out[(size_t)b * H_ + h] = acc / s;
}

// ---------------------------------------------------------------------------
// Launch
// ---------------------------------------------------------------------------
extern "C" void kernel_launch(void* const* d_in, const int* in_sizes, int n_in,
                              void* d_out, int out_size)
{
    const float* x     = (const float*)d_in[0];
    const float* h_w1  = (const float*)d_in[1];
    const float* h_b1  = (const float*)d_in[2];
    const float* h_w2  = (const float*)d_in[3];
    const float* h_b2  = (const float*)d_in[4];
    const float* h_w3  = (const float*)d_in[5];
    const float* h_b3  = (const float*)d_in[6];
    const float* i_w1  = (const float*)d_in[7];
    const float* i_b1  = (const float*)d_in[8];
    const float* i_w2  = (const float*)d_in[9];
    const float* i_b2  = (const float*)d_in[10];
    const float* i_w3  = (const float*)d_in[11];
    const float* i_b3  = (const float*)d_in[12];
    const float* att_w = (const float*)d_in[13];
    const float* att_b = (const float*)d_in[14];
    float* out = (float*)d_out;

    float *t1, *t2, *xin, *hs;
    cudaGetSymbolAddress((void**)&t1,  g_t1);
    cudaGetSymbolAddress((void**)&t2,  g_t2);
    cudaGetSymbolAddress((void**)&xin, g_xin);
    cudaGetSymbolAddress((void**)&hs,  g_hs);
    float* aw = t1;   // reuse t1 for attention logits in Phase C

    // ---------------- Phase A: input MLP over all B*T rows ----------------
    gemm_kernel<1,false,false><<<dim3(W1_/128, BT_/128), 256>>>(
        x,  i_w1, i_b1, nullptr, t1,  BT_, W1_, IN_);
    gemm_kernel<1,false,false><<<dim3(W2_/128, BT_/128), 256>>>(
        t1, i_w2, i_b2, nullptr, t2,  BT_, W2_, W1_);
    gemm_kernel<0,true ,false><<<dim3(H_/128, BT_/128), 256>>>(
        t2, i_w3, i_b3, nullptr, xin, BT_, H_, W2_);

    // ---------------- Phase B: persistent recurrence (ONE launch) ---------
    cudaFuncSetAttribute(recurrence_kernel,
                         cudaFuncAttributeMaxDynamicSharedMemorySize, SMEM_BYTES);
    recurrence_kernel<<<128, 256, SMEM_BYTES>>>(
        h_w1, h_b1, h_w2, h_b2, h_w3, h_b3, xin, hs);

    // ---------------- Phase C: attention pooling --------------------------
    gemm_kernel<2,false,false><<<dim3(H_/128, BT_/128), 256>>>(
        hs, att_w, att_b, nullptr, aw, BT_, H_, H_);
    attn_reduce_kernel<<<B_, H_>>>(aw, hs, out);
}

// round 12
// speedup vs baseline: 1.3681x; 1.0814x over previous
#include <cuda_runtime.h>
#include <cuda_bf16.h>
#include <cstddef>
#include <cstdint>

// Problem dims (fixed)
#define B_   256
#define T_   512
#define IN_  128
#define H_   256
#define W1_  512
#define W2_  512
#define BT_  (B_ * T_)   // 131072

// ---------------------------------------------------------------------------
// Scratch (device globals — no allocations allowed anywhere)
// ---------------------------------------------------------------------------
__device__ float g_aw [(size_t)BT_ * H_];   // Phase C attention logits
__device__ float g_xin[(size_t)BT_ * H_];   // input-MLP output, layout [T, B, H]
__device__ float g_hs [(size_t)BT_ * H_];   // all hidden states,  layout [T, B, H]
// bf16 hi/lo split operands for Phase A tensor-core GEMMs
__device__ __nv_bfloat16 g_xhi [(size_t)BT_ * IN_],  g_xlo [(size_t)BT_ * IN_];
__device__ __nv_bfloat16 g_a1hi[(size_t)BT_ * W1_],  g_a1lo[(size_t)BT_ * W1_];
__device__ __nv_bfloat16 g_a2hi[(size_t)BT_ * W2_],  g_a2lo[(size_t)BT_ * W2_];
__device__ __nv_bfloat16 g_w1Thi[W1_ * IN_], g_w1Tlo[W1_ * IN_];
__device__ __nv_bfloat16 g_w2Thi[W2_ * W1_], g_w2Tlo[W2_ * W1_];
__device__ __nv_bfloat16 g_w3Thi[H_  * W2_], g_w3Tlo[H_  * W2_];

// ---------------------------------------------------------------------------
// f32x2 packed helpers
// ---------------------------------------------------------------------------
typedef unsigned long long u64;

__device__ __forceinline__ u64 fma2(u64 a, u64 b, u64 c) {
    u64 d;
    asm("fma.rn.f32x2 %0, %1, %2, %3;" : "=l"(d) : "l"(a), "l"(b), "l"(c));
    return d;
}
__device__ __forceinline__ u64 dup2(float x) {
    u64 d; unsigned int u = __float_as_uint(x);
    asm("mov.b64 %0, {%1, %1};" : "=l"(d) : "r"(u));
    return d;
}
__device__ __forceinline__ void unpack2(u64 v, float& lo, float& hi) {
    unsigned int a, b;
    asm("mov.b64 {%0, %1}, %2;" : "=r"(a), "=r"(b) : "l"(v));
    lo = __uint_as_float(a); hi = __uint_as_float(b);
}

// ---------------------------------------------------------------------------
// mbarrier / bulk-async / cluster helpers (Phase B)
// ---------------------------------------------------------------------------
__device__ __forceinline__ uint32_t smem_u32(const void* p) {
    uint32_t a;
    asm("{ .reg .u64 t; cvta.to.shared.u64 t, %1; cvt.u32.u64 %0, t; }"
        : "=r"(a) : "l"(p));
    return a;
}
__device__ __forceinline__ void mbar_init(uint32_t mbar, uint32_t count) {
    asm volatile("mbarrier.init.shared.b64 [%0], %1;" :: "r"(mbar), "r"(count) : "memory");
}
__device__ __forceinline__ void mbar_expect_tx(uint32_t mbar, uint32_t bytes) {
    asm volatile("mbarrier.arrive.expect_tx.shared.b64 _, [%0], %1;"
                 :: "r"(mbar), "r"(bytes) : "memory");
}
__device__ __forceinline__ void mbar_wait_parity(uint32_t mbar, uint32_t parity) {
    asm volatile(
        "{\n\t"
        ".reg .pred P;\n\t"
        "WAIT_%=:\n\t"
        "mbarrier.try_wait.parity.shared.b64 P, [%0], %1, 0x989680;\n\t"
        "@P bra.uni DONE_%=;\n\t"
        "bra.uni WAIT_%=;\n\t"
        "DONE_%=:\n\t"
        "}"
        :: "r"(mbar), "r"(parity) : "memory");
}
__device__ __forceinline__ uint32_t mapa_rank(uint32_t addr, uint32_t rank) {
    uint32_t r;
    asm("mapa.shared::cluster.u32 %0, %1, %2;" : "=r"(r) : "r"(addr), "r"(rank));
    return r;
}
__device__ __forceinline__ void mbar_arrive_remote(uint32_t cluster_addr) {
    asm volatile("mbarrier.arrive.shared::cluster.b64 _, [%0];"
                 :: "r"(cluster_addr) : "memory");
}
__device__ __forceinline__ void bulk_g2s_mc(uint32_t dst_smem, const void* src_gmem,
                                            uint32_t bytes, uint32_t mbar, uint16_t mask) {
    asm volatile(
        "cp.async.bulk.shared::cluster.global.mbarrier::complete_tx::bytes.multicast::cluster "
        "[%0], [%1], %2, [%3], %4;"
        :: "r"(dst_smem), "l"(src_gmem), "r"(bytes), "r"(mbar), "h"(mask) : "memory");
}
__device__ __forceinline__ uint32_t cluster_rank() {
    uint32_t r; asm("mov.u32 %0, %%cluster_ctarank;" : "=r"(r)); return r;
}
#define CLUSTER_SYNC() do { \
    asm volatile("barrier.cluster.arrive.aligned;" ::: "memory"); \
    asm volatile("barrier.cluster.wait.aligned;"   ::: "memory"); \
} while (0)

// ---------------------------------------------------------------------------
// bf16 hi/lo split helpers + kernels
// ---------------------------------------------------------------------------
__device__ __forceinline__ void split_bf16(float v, __nv_bfloat16& h, __nv_bfloat16& l) {
    h = __float2bfloat16(v);
    l = __float2bfloat16(v - __bfloat162float(h));
}

__global__ void split_kernel(const float* __restrict__ in, __nv_bfloat16* __restrict__ hi,
                             __nv_bfloat16* __restrict__ lo, int n)
{
    int i = (blockIdx.x * 256 + threadIdx.x) * 4;
    if (i >= n) return;
    float4 v = *(const float4*)(in + i);
    __nv_bfloat16 h0, l0, h1, l1, h2, l2, h3, l3;
    split_bf16(v.x, h0, l0); split_bf16(v.y, h1, l1);
    split_bf16(v.z, h2, l2); split_bf16(v.w, h3, l3);
    __nv_bfloat162 hp0 = {h0, h1}, hp1 = {h2, h3}, lp0 = {l0, l1}, lp1 = {l2, l3};
    *(uint2*)(hi + i) = make_uint2(*(uint32_t*)&hp0, *(uint32_t*)&hp1);
    *(uint2*)(lo + i) = make_uint2(*(uint32_t*)&lp0, *(uint32_t*)&lp1);
}

// in: [Kd, Nd] row-major -> out transposed [Nd, Kd] hi/lo bf16
__global__ void splitT_kernel(const float* __restrict__ in, __nv_bfloat16* __restrict__ hiT,
                              __nv_bfloat16* __restrict__ loT, int Kd, int Nd)
{
    int idx = blockIdx.x * 256 + threadIdx.x;
    if (idx >= Kd * Nd) return;
    int k = idx / Nd, n2 = idx - k * Nd;
    __nv_bfloat16 h, l;
    split_bf16(in[idx], h, l);
    hiT[(size_t)n2 * Kd + k] = h;
    loT[(size_t)n2 * Kd + k] = l;
}

// ---------------------------------------------------------------------------
// Phase A: bf16-split GEMM via legacy mma.sync (m16n8k16, bf16 -> fp32).
//   D[M,N] = act(A @ W + bias);  A as (Ahi,Alo)[M,K] K-major,
//   W as (Bhi,Blo)[N,K] (transposed).  D = Ahi*Bhi^T + Ahi*Blo^T + Alo*Bhi^T.
// CTA tile 128x128, BK=32, 8 warps as 2(M)x4(N) -> warp tile 64x32.
// OUTSPLIT: write (Chi,Clo) bf16 for the next layer.
// !OUTSPLIT: write fp32 with PERM row b*T+t -> t*B+b (produces xin [T,B,H]).
// ---------------------------------------------------------------------------
#define PADK 36   // bf16 per smem tile row (32 data + 4 pad)

__device__ __forceinline__ void mma_bf16(float* d, const uint32_t* a, const uint32_t* b) {
    asm volatile(
        "mma.sync.aligned.m16n8k16.row.col.f32.bf16.bf16.f32 "
        "{%0,%1,%2,%3}, {%4,%5,%6,%7}, {%8,%9}, {%0,%1,%2,%3};"
        : "+f"(d[0]), "+f"(d[1]), "+f"(d[2]), "+f"(d[3])
        : "r"(a[0]), "r"(a[1]), "r"(a[2]), "r"(a[3]), "r"(b[0]), "r"(b[1]));
}

template <int ACT, bool OUTSPLIT>
__global__ void __launch_bounds__(256)
mm_mma_kernel(const __nv_bfloat16* __restrict__ Ahi, const __nv_bfloat16* __restrict__ Alo,
              const __nv_bfloat16* __restrict__ Bhi, const __nv_bfloat16* __restrict__ Blo,
              const float* __restrict__ bias,
              __nv_bfloat16* __restrict__ Chi, __nv_bfloat16* __restrict__ Clo,
              float* __restrict__ Cf, int M, int N, int K)
{
    __shared__ __align__(16) __nv_bfloat16 sAh[128 * PADK], sAl[128 * PADK];
    __shared__ __align__(16) __nv_bfloat16 sBh[128 * PADK], sBl[128 * PADK];

    const int tid = threadIdx.x, lane = tid & 31, wid = tid >> 5;
    const int wm = wid >> 2, wn = wid & 3;      // 2 x 4 warp grid
    const int bn = blockIdx.x, bm = blockIdx.y;

    float acc[4][4][4];
#pragma unroll
    for (int i = 0; i < 4; i++)
#pragma unroll
        for (int j = 0; j < 4; j++)
#pragma unroll
            for (int q = 0; q < 4; q++) acc[i][j][q] = 0.f;

    const __nv_bfloat16* aH = Ahi + (size_t)(bm * 128) * K;
    const __nv_bfloat16* aL = Alo + (size_t)(bm * 128) * K;
    const __nv_bfloat16* bH = Bhi + (size_t)(bn * 128) * K;
    const __nv_bfloat16* bL = Blo + (size_t)(bn * 128) * K;

    const int frow = lane >> 2;            // 0..7
    const int fcol = (lane & 3) * 2;       // 0,2,4,6

    for (int k0 = 0; k0 < K; k0 += 32) {
        // fill 4 tiles: 128 rows x 32 bf16 each (512 groups of 8 bf16)
#pragma unroll
        for (int g = tid; g < 512; g += 256) {
            const int row = g >> 2;
            const int kg  = (g & 3) * 8;
            const size_t go = (size_t)row * K + k0 + kg;
            const int so = row * PADK + kg;
            ulonglong2 v;
            v = *(const ulonglong2*)(aH + go);
            *(u64*)(sAh + so) = v.x; *(u64*)(sAh + so + 4) = v.y;
            v = *(const ulonglong2*)(aL + go);
            *(u64*)(sAl + so) = v.x; *(u64*)(sAl + so + 4) = v.y;
            v = *(const ulonglong2*)(bH + go);
            *(u64*)(sBh + so) = v.x; *(u64*)(sBh + so + 4) = v.y;
            v = *(const ulonglong2*)(bL + go);
            *(u64*)(sBl + so) = v.x; *(u64*)(sBl + so + 4) = v.y;
        }
        __syncthreads();

#pragma unroll
        for (int ks = 0; ks < 2; ks++) {
            const int kb = ks * 16 + fcol;
            uint32_t Afh[4][4], Afl[4][4], Bfh[4][2], Bfl[4][2];
#pragma unroll
            for (int mt = 0; mt < 4; mt++) {
                const int r0 = (wm * 64 + mt * 16 + frow) * PADK + kb;
                const int r1 = r0 + 8 * PADK;
                Afh[mt][0] = *(const uint32_t*)(sAh + r0);
                Afh[mt][1] = *(const uint32_t*)(sAh + r1);
                Afh[mt][2] = *(const uint32_t*)(sAh + r0 + 8);
                Afh[mt][3] = *(const uint32_t*)(sAh + r1 + 8);
                Afl[mt][0] = *(const uint32_t*)(sAl + r0);
                Afl[mt][1] = *(const uint32_t*)(sAl + r1);
                Afl[mt][2] = *(const uint32_t*)(sAl + r0 + 8);
                Afl[mt][3] = *(const uint32_t*)(sAl + r1 + 8);
            }
#pragma unroll
            for (int nt = 0; nt < 4; nt++) {
                const int n0 = (wn * 32 + nt * 8 + frow) * PADK + kb;
                Bfh[nt][0] = *(const uint32_t*)(sBh + n0);
                Bfh[nt][1] = *(const uint32_t*)(sBh + n0 + 8);
                Bfl[nt][0] = *(const uint32_t*)(sBl + n0);
                Bfl[nt][1] = *(const uint32_t*)(sBl + n0 + 8);
            }
#pragma unroll
            for (int mt = 0; mt < 4; mt++)
#pragma unroll
                for (int nt = 0; nt < 4; nt++) {
                    mma_bf16(acc[mt][nt], Afh[mt], Bfh[nt]);
                    mma_bf16(acc[mt][nt], Afh[mt], Bfl[nt]);
                    mma_bf16(acc[mt][nt], Afl[mt], Bfh[nt]);
                }
        }
        __syncthreads();
    }

    // Epilogue: lane holds rows (r, r+8), cols (c, c+1) per frag
#pragma unroll
    for (int mt = 0; mt < 4; mt++) {
        const int rA = bm * 128 + wm * 64 + mt * 16 + frow;
        const int rB = rA + 8;
#pragma unroll
        for (int nt = 0; nt < 4; nt++) {
            const int c = bn * 128 + wn * 32 + nt * 8 + fcol;
            float v00 = acc[mt][nt][0] + bias[c];
            float v01 = acc[mt][nt][1] + bias[c + 1];
            float v10 = acc[mt][nt][2] + bias[c];
            float v11 = acc[mt][nt][3] + bias[c + 1];
            if (ACT == 1) {
                v00 = fmaxf(v00, 0.f); v01 = fmaxf(v01, 0.f);
                v10 = fmaxf(v10, 0.f); v11 = fmaxf(v11, 0.f);
            }
            if (OUTSPLIT) {
                __nv_bfloat16 h0, l0, h1, l1;
                split_bf16(v00, h0, l0); split_bf16(v01, h1, l1);
                uint32_t hp = (uint32_t)__bfloat16_as_ushort(h0) |
                              ((uint32_t)__bfloat16_as_ushort(h1) << 16);
                uint32_t lp = (uint32_t)__bfloat16_as_ushort(l0) |
                              ((uint32_t)__bfloat16_as_ushort(l1) << 16);
                *(uint32_t*)(Chi + (size_t)rA * N + c) = hp;
                *(uint32_t*)(Clo + (size_t)rA * N + c) = lp;
                split_bf16(v10, h0, l0); split_bf16(v11, h1, l1);
                hp = (uint32_t)__bfloat16_as_ushort(h0) |
                     ((uint32_t)__bfloat16_as_ushort(h1) << 16);
                lp = (uint32_t)__bfloat16_as_ushort(l0) |
                     ((uint32_t)__bfloat16_as_ushort(l1) << 16);
                *(uint32_t*)(Chi + (size_t)rB * N + c) = hp;
                *(uint32_t*)(Clo + (size_t)rB * N + c) = lp;
            } else {
                // PERM: row = b*T + t -> orow = t*B + b
                const int bA = rA >> 9, tA = rA & (T_ - 1);
                const int bB = rB >> 9, tB = rB & (T_ - 1);
                *(float2*)(Cf + (size_t)(tA * B_ + bA) * N + c) = make_float2(v00, v01);
                *(float2*)(Cf + (size_t)(tB * B_ + bB) * N + c) = make_float2(v10, v11);
            }
        }
    }
}

// ---------------------------------------------------------------------------
// fp32 tiled GEMM with packed f32x2 compute (verified; used for Phase C)
// ---------------------------------------------------------------------------
template <int ACT>
__global__ void __launch_bounds__(256)
gemm_kernel(const float* __restrict__ A, const float* __restrict__ W,
            const float* __restrict__ bias, float* __restrict__ C,
            int M, int N, int K)
{
    constexpr int BM = 128, BN = 128, BK = 16, TM = 8, TN = 8;
    constexpr int THREADS = 256;
    __shared__ float As[BK][BM];
    __shared__ float Bs[BK][BN];

    const int tid  = threadIdx.x;
    const int bcol = blockIdx.x;
    const int brow = blockIdx.y;
    const int tx   = tid % (BN / TN);
    const int ty   = tid / (BN / TN);

    u64 acc2[TM][TN / 2];
#pragma unroll
    for (int i = 0; i < TM; i++)
#pragma unroll
        for (int j = 0; j < TN / 2; j++) acc2[i][j] = 0ull;

    const float* Ab = A + (size_t)brow * BM * K;
    const float* Wb = W + (size_t)bcol * BN;

    for (int k0 = 0; k0 < K; k0 += BK) {
#pragma unroll
        for (int i = tid * 4; i < BM * BK; i += THREADS * 4) {
            int r = i / BK, c = i % BK;
            float4 v = *(const float4*)(Ab + (size_t)r * K + k0 + c);
            As[c + 0][r] = v.x; As[c + 1][r] = v.y;
            As[c + 2][r] = v.z; As[c + 3][r] = v.w;
        }
#pragma unroll
        for (int i = tid * 4; i < BK * BN; i += THREADS * 4) {
            int r = i / BN, c = i % BN;
            float4 v = *(const float4*)(Wb + (size_t)(k0 + r) * N + c);
            *(float4*)&Bs[r][c] = v;
        }
        __syncthreads();

#pragma unroll
        for (int kk = 0; kk < BK; kk++) {
            ulonglong2 bb0 = *(const ulonglong2*)&Bs[kk][tx * TN];
            ulonglong2 bb1 = *(const ulonglong2*)&Bs[kk][tx * TN + 4];
            u64 bp[TN / 2] = { bb0.x, bb0.y, bb1.x, bb1.y };
            float4 a0 = *(const float4*)&As[kk][ty * TM];
            float4 a1 = *(const float4*)&As[kk][ty * TM + 4];
            u64 ad[TM];
            ad[0] = dup2(a0.x); ad[1] = dup2(a0.y);
            ad[2] = dup2(a0.z); ad[3] = dup2(a0.w);
            ad[4] = dup2(a1.x); ad[5] = dup2(a1.y);
            ad[6] = dup2(a1.z); ad[7] = dup2(a1.w);
#pragma unroll
            for (int i = 0; i < TM; i++)
#pragma unroll
                for (int j = 0; j < TN / 2; j++)
                    acc2[i][j] = fma2(ad[i], bp[j], acc2[i][j]);
        }
        __syncthreads();
    }

#pragma unroll
    for (int i = 0; i < TM; i++) {
        int row = brow * BM + ty * TM + i;
        float* Crow = C + (size_t)row * N;
#pragma unroll
        for (int j = 0; j < TN / 2; j++) {
            int col = bcol * BN + tx * TN + j * 2;
            float v0, v1;
            unpack2(acc2[i][j], v0, v1);
            v0 += bias[col];
            v1 += bias[col + 1];
            if (ACT == 2) { v0 = tanhf(v0); v1 = tanhf(v1); }
            Crow[col]     = v0;
            Crow[col + 1] = v1;
        }
    }
}

// ---------------------------------------------------------------------------
// Phase B: persistent recurrence (verified Round 10 config — UNCHANGED).
// ---------------------------------------------------------------------------
#define NSTAGE      4
#define CHUNK_F     8192
#define CHUNK_BYTES (CHUNK_F * 4)
#define CHUNKS_PER_STEP 64
#define TOTAL_CHUNKS    (T_ * CHUNKS_PER_STEP)
#define MC_MASK     0xFu

#define SM_WBUF  0
#define SM_HT    (NSTAGE * CHUNK_F)
#define SM_Y1T   (SM_HT + H_ * 2)
#define SM_Y2T   (SM_Y1T + W1_ * 2)
#define SM_B1    (SM_Y2T + W2_ * 2)
#define SM_B2    (SM_B1 + W1_)
#define SM_B3    (SM_B2 + W2_)
#define SM_FULL  (SM_B3 + H_)
#define SM_EMPTY (SM_FULL + 2 * NSTAGE)
#define SMEM_FLOATS (SM_EMPTY + 2 * NSTAGE)
#define SMEM_BYTES  (SMEM_FLOATS * 4)

struct WSrc { const float* w1; const float* w2; const float* w3; };

__device__ __forceinline__ const float* chunk_src(const WSrc& w, int cg) {
    int c = cg & (CHUNKS_PER_STEP - 1);
    if (c < 16)      return w.w1 + (size_t)c * 16 * W1_;
    else if (c < 48) return w.w2 + (size_t)(c - 16) * 16 * W2_;
    else             return w.w3 + (size_t)(c - 48) * 32 * H_;
}

__global__ void __launch_bounds__(256, 1) __cluster_dims__(4, 1, 1)
recurrence_kernel(const float* __restrict__ w1, const float* __restrict__ b1,
                  const float* __restrict__ w2, const float* __restrict__ b2,
                  const float* __restrict__ w3, const float* __restrict__ b3,
                  const float* __restrict__ xin, float* __restrict__ hs)
{
    extern __shared__ float smemf[];
    float* wbuf = smemf + SM_WBUF;
    float* hT   = smemf + SM_HT;
    float* y1T  = smemf + SM_Y1T;
    float* y2T  = smemf + SM_Y2T;
    float* bs1  = smemf + SM_B1;
    float* bs2  = smemf + SM_B2;
    float* bs3  = smemf + SM_B3;
    const uint32_t fullb  = smem_u32(smemf + SM_FULL);
    const uint32_t emptyb = smem_u32(smemf + SM_EMPTY);

    const int tid = threadIdx.x;
    const int b0  = blockIdx.x * 2;
    const uint32_t rank = cluster_rank();
    WSrc wsrc = { w1, w2, w3 };

    for (int i = tid; i < W1_; i += 256) bs1[i] = b1[i];
    for (int i = tid; i < W2_; i += 256) bs2[i] = b2[i];
    for (int i = tid; i < H_;  i += 256) bs3[i] = b3[i];
    for (int i = tid; i < H_ * 2; i += 256) hT[i] = 0.f;
    if (tid == 0) {
#pragma unroll
        for (int s = 0; s < NSTAGE; s++) {
            mbar_init(fullb  + s * 8, 1);
            mbar_init(emptyb + s * 8, NSTAGE);
        }
    }
    __syncthreads();

    if (tid == 0) {
#pragma unroll
        for (int s = 0; s < NSTAGE; s++) mbar_expect_tx(fullb + s * 8, CHUNK_BYTES);
    }
    CLUSTER_SYNC();
    if (tid == 0) {
        bulk_g2s_mc(smem_u32(wbuf + rank * CHUNK_F), chunk_src(wsrc, (int)rank),
                    CHUNK_BYTES, fullb + rank * 8, MC_MASK);
    }

    int chunk = 0;

#define PAIR_BOOKKEEP()                                                         \
    do {                                                                        \
        __syncthreads();                                                        \
        if (tid == 0) {                                                         \
            _Pragma("unroll")                                                   \
            for (int q = 0; q < 2; q++) {                                       \
                const int cq = chunk + q;                                       \
                if (cq + NSTAGE < TOTAL_CHUNKS) {                               \
                    const int s_ = cq & (NSTAGE - 1);                           \
                    mbar_expect_tx(fullb + s_ * 8, CHUNK_BYTES);                \
                    mbar_arrive_remote(mapa_rank(emptyb + s_ * 8, (uint32_t)s_));\
                    if (rank == (uint32_t)s_) {                                 \
                        mbar_wait_parity(emptyb + s_ * 8, (cq >> 2) & 1);       \
                        bulk_g2s_mc(smem_u32(wbuf + s_ * CHUNK_F),              \
                                    chunk_src(wsrc, cq + NSTAGE),               \
                                    CHUNK_BYTES, fullb + s_ * 8, MC_MASK);      \
                    }                                                           \
                }                                                               \
            }                                                                   \
        }                                                                       \
        chunk += 2;                                                             \
    } while (0)

    for (int t = 0; t < T_; t++) {
        const int c0 = tid * 2;

        {   // Layer 1: K=256, 8 pairs
            u64 a0 = 0, a1 = 0;
            for (int jp = 0; jp < 8; jp++) {
                const int s0 = chunk & (NSTAGE - 1);
                const int s1 = (chunk + 1) & (NSTAGE - 1);
                mbar_wait_parity(fullb + s0 * 8, (chunk >> 2) & 1);
                mbar_wait_parity(fullb + s1 * 8, ((chunk + 1) >> 2) & 1);
                const float* wb0 = wbuf + s0 * CHUNK_F;
                const float* wb1 = wbuf + s1 * CHUNK_F;
#pragma unroll
                for (int kk = 0; kk < 16; kk++) {
                    const int k = jp * 32 + kk;
                    u64 r = *(const u64*)(hT + k * 2);
                    float2 w = *(const float2*)(wb0 + kk * W1_ + c0);
                    a0 = fma2(r, dup2(w.x), a0);
                    a1 = fma2(r, dup2(w.y), a1);
                }
#pragma unroll
                for (int kk = 0; kk < 16; kk++) {
                    const int k = jp * 32 + 16 + kk;
                    u64 r = *(const u64*)(hT + k * 2);
                    float2 w = *(const float2*)(wb1 + kk * W1_ + c0);
                    a0 = fma2(r, dup2(w.x), a0);
                    a1 = fma2(r, dup2(w.y), a1);
                }
                PAIR_BOOKKEEP();
            }
            float v0, v1;
            const float bb0 = bs1[c0], bb1 = bs1[c0 + 1];
            unpack2(a0, v0, v1);
            *(float2*)(y1T + c0 * 2) =
                make_float2(fmaxf(v0 + bb0, 0.f), fmaxf(v1 + bb0, 0.f));
            unpack2(a1, v0, v1);
            *(float2*)(y1T + (c0 + 1) * 2) =
                make_float2(fmaxf(v0 + bb1, 0.f), fmaxf(v1 + bb1, 0.f));
        }
        __syncthreads();

        {   // Layer 2: K=512, 16 pairs
            u64 a0 = 0, a1 = 0;
            for (int jp = 0; jp < 16; jp++) {
                const int s0 = chunk & (NSTAGE - 1);
                const int s1 = (chunk + 1) & (NSTAGE - 1);
                mbar_wait_parity(fullb + s0 * 8, (chunk >> 2) & 1);
                mbar_wait_parity(fullb + s1 * 8, ((chunk + 1) >> 2) & 1);
                const float* wb0 = wbuf + s0 * CHUNK_F;
                const float* wb1 = wbuf + s1 * CHUNK_F;
#pragma unroll
                for (int kk = 0; kk < 16; kk++) {
                    const int k = jp * 32 + kk;
                    u64 r = *(const u64*)(y1T + k * 2);
                    float2 w = *(const float2*)(wb0 + kk * W2_ + c0);
                    a0 = fma2(r, dup2(w.x), a0);
                    a1 = fma2(r, dup2(w.y), a1);
                }
#pragma unroll
                for (int kk = 0; kk < 16; kk++) {
                    const int k = jp * 32 + 16 + kk;
                    u64 r = *(const u64*)(y1T + k * 2);
                    float2 w = *(const float2*)(wb1 + kk * W2_ + c0);
                    a0 = fma2(r, dup2(w.x), a0);
                    a1 = fma2(r, dup2(w.y), a1);
                }
                PAIR_BOOKKEEP();
            }
            float v0, v1;
            const float bb0 = bs2[c0], bb1 = bs2[c0 + 1];
            unpack2(a0, v0, v1);
            *(float2*)(y2T + c0 * 2) =
                make_float2(fmaxf(v0 + bb0, 0.f), fmaxf(v1 + bb0, 0.f));
            unpack2(a1, v0, v1);
            *(float2*)(y2T + (c0 + 1) * 2) =
                make_float2(fmaxf(v0 + bb1, 0.f), fmaxf(v1 + bb1, 0.f));
        }
        __syncthreads();

        {   // Layer 3: K=512, 8 pairs (64 k per pair)
            const int c = tid;
            u64 ae = 0, ao = 0;
            for (int jp = 0; jp < 8; jp++) {
                const int s0 = chunk & (NSTAGE - 1);
                const int s1 = (chunk + 1) & (NSTAGE - 1);
                mbar_wait_parity(fullb + s0 * 8, (chunk >> 2) & 1);
                mbar_wait_parity(fullb + s1 * 8, ((chunk + 1) >> 2) & 1);
                const float* wb0 = wbuf + s0 * CHUNK_F;
                const float* wb1 = wbuf + s1 * CHUNK_F;
#pragma unroll
                for (int kk = 0; kk < 32; kk += 2) {
                    const int k = jp * 64 + kk;
                    u64 r0 = *(const u64*)(y2T + k * 2);
                    u64 r1 = *(const u64*)(y2T + (k + 1) * 2);
                    ae = fma2(r0, dup2(wb0[kk * H_ + c]),       ae);
                    ao = fma2(r1, dup2(wb0[(kk + 1) * H_ + c]), ao);
                }
#pragma unroll
                for (int kk = 0; kk < 32; kk += 2) {
                    const int k = jp * 64 + 32 + kk;
                    u64 r0 = *(const u64*)(y2T + k * 2);
                    u64 r1 = *(const u64*)(y2T + (k + 1) * 2);
                    ae = fma2(r0, dup2(wb1[kk * H_ + c]),       ae);
                    ao = fma2(r1, dup2(wb1[(kk + 1) * H_ + c]), ao);
                }
                PAIR_BOOKKEEP();
            }
            float e0, e1, o0, o1;
            unpack2(ae, e0, e1); unpack2(ao, o0, o1);
            const float bb = bs3[c];
            const float* xr = xin + (size_t)t * B_ * H_ + (size_t)b0 * H_ + c;
            float*       hr = hs  + (size_t)t * B_ * H_ + (size_t)b0 * H_ + c;
            float v0 = tanhf(e0 + o0 + bb + xr[0 * H_]);
            float v1 = tanhf(e1 + o1 + bb + xr[1 * H_]);
            hr[0 * H_] = v0; hr[1 * H_] = v1;
            *(float2*)(hT + c * 2) = make_float2(v0, v1);
        }
        __syncthreads();
    }

    CLUSTER_SYNC();
#undef PAIR_BOOKKEEP
}

// ---------------------------------------------------------------------------
// Phase C reduction: online softmax over T (axis 0) + weighted sum of hs.
// ---------------------------------------------------------------------------
__global__ void attn_reduce_kernel(const float* __restrict__ aw,
                                   const float* __restrict__ hs,
                                   float* __restrict__ out)
{
    const int b = blockIdx.x;
    const int h = threadIdx.x;
    float m = -1e30f, s = 0.f, acc = 0.f;
    for (int t = 0; t < T_; t++) {
        size_t idx = ((size_t)t * B_ + b) * H_ + h;
        float a  = aw[idx];
        float hv = hs[idx];
        if (a > m) {
            float c = __expf(m - a);
            s   = s * c + 1.f;
            acc = acc * c + hv;
            m   = a;
        } else {
            float e = __expf(a - m);
            s   += e;
            acc += e * hv;
        }
    }
    out[(size_t)b * H_ + h] = acc / s;
}

// ---------------------------------------------------------------------------
// Launch
// ---------------------------------------------------------------------------
extern "C" void kernel_launch(void* const* d_in, const int* in_sizes, int n_in,
                              void* d_out, int out_size)
{
    const float* x     = (const float*)d_in[0];
    const float* h_w1  = (const float*)d_in[1];
    const float* h_b1  = (const float*)d_in[2];
    const float* h_w2  = (const float*)d_in[3];
    const float* h_b2  = (const float*)d_in[4];
    const float* h_w3  = (const float*)d_in[5];
    const float* h_b3  = (const float*)d_in[6];
    const float* i_w1  = (const float*)d_in[7];
    const float* i_b1  = (const float*)d_in[8];
    const float* i_w2  = (const float*)d_in[9];
    const float* i_b2  = (const float*)d_in[10];
    const float* i_w3  = (const float*)d_in[11];
    const float* i_b3  = (const float*)d_in[12];
    const float* att_w = (const float*)d_in[13];
    const float* att_b = (const float*)d_in[14];
    float* out = (float*)d_out;

    float *aw, *xin, *hs;
    cudaGetSymbolAddress((void**)&aw,  g_aw);
    cudaGetSymbolAddress((void**)&xin, g_xin);
    cudaGetSymbolAddress((void**)&hs,  g_hs);
    __nv_bfloat16 *xhi, *xlo, *a1hi, *a1lo, *a2hi, *a2lo;
    __nv_bfloat16 *w1Thi, *w1Tlo, *w2Thi, *w2Tlo, *w3Thi, *w3Tlo;
    cudaGetSymbolAddress((void**)&xhi,  g_xhi);  cudaGetSymbolAddress((void**)&xlo,  g_xlo);
    cudaGetSymbolAddress((void**)&a1hi, g_a1hi); cudaGetSymbolAddress((void**)&a1lo, g_a1lo);
    cudaGetSymbolAddress((void**)&a2hi, g_a2hi); cudaGetSymbolAddress((void**)&a2lo, g_a2lo);
    cudaGetSymbolAddress((void**)&w1Thi, g_w1Thi); cudaGetSymbolAddress((void**)&w1Tlo, g_w1Tlo);
    cudaGetSymbolAddress((void**)&w2Thi, g_w2Thi); cudaGetSymbolAddress((void**)&w2Tlo, g_w2Tlo);
    cudaGetSymbolAddress((void**)&w3Thi, g_w3Thi); cudaGetSymbolAddress((void**)&w3Tlo, g_w3Tlo);

    // ---------------- Phase A: bf16-split mma.sync input MLP --------------
    split_kernel<<<(BT_ * IN_) / 1024, 256>>>(x, xhi, xlo, BT_ * IN_);
    splitT_kernel<<<(IN_ * W1_) / 256, 256>>>(i_w1, w1Thi, w1Tlo, IN_, W1_);
    splitT_kernel<<<(W1_ * W2_) / 256, 256>>>(i_w2, w2Thi, w2Tlo, W1_, W2_);
    splitT_kernel<<<(W2_ * H_)  / 256, 256>>>(i_w3, w3Thi, w3Tlo, W2_, H_);

    mm_mma_kernel<1, true><<<dim3(W1_ / 128, BT_ / 128), 256>>>(
        xhi, xlo, w1Thi, w1Tlo, i_b1, a1hi, a1lo, nullptr, BT_, W1_, IN_);
    mm_mma_kernel<1, true><<<dim3(W2_ / 128, BT_ / 128), 256>>>(
        a1hi, a1lo, w2Thi, w2Tlo, i_b2, a2hi, a2lo, nullptr, BT_, W2_, W1_);
    mm_mma_kernel<0, false><<<dim3(H_ / 128, BT_ / 128), 256>>>(
        a2hi, a2lo, w3Thi, w3Tlo, i_b3, nullptr, nullptr, xin, BT_, H_, W2_);

    // ---------------- Phase B: persistent recurrence (ONE launch) ---------
    cudaFuncSetAttribute(recurrence_kernel,
                         cudaFuncAttributeMaxDynamicSharedMemorySize, SMEM_BYTES);
    recurrence_kernel<<<128, 256, SMEM_BYTES>>>(
        h_w1, h_b1, h_w2, h_b2, h_w3, h_b3, xin, hs);

    // ---------------- Phase C: attention pooling --------------------------
    gemm_kernel<2><<<dim3(H_ / 128, BT_ / 128), 256>>>(
        hs, att_w, att_b, aw, BT_, H_, H_);
    attn_reduce_kernel<<<B_, H_>>>(aw, hs, out);
}

// round 14
// speedup vs baseline: 1.4650x; 1.0709x over previous
#include <cuda_runtime.h>
#include <cuda_bf16.h>
#include <cstddef>
#include <cstdint>

// Problem dims (fixed)
#define B_   256
#define T_   512
#define IN_  128
#define H_   256
#define W1_  512
#define W2_  512
#define BT_  (B_ * T_)   // 131072

// ---------------------------------------------------------------------------
// Scratch (device globals — no allocations allowed anywhere)
// ---------------------------------------------------------------------------
__device__ float g_aw [(size_t)BT_ * H_];   // Phase C attention logits
__device__ float g_xin[(size_t)BT_ * H_];   // input-MLP output, layout [T, B, H]
__device__ float g_hs [(size_t)BT_ * H_];   // all hidden states,  layout [T, B, H]
// bf16 hi/lo split operands (Phase A GEMMs; a2* reused for Phase C hs-split)
__device__ __nv_bfloat16 g_xhi [(size_t)BT_ * IN_],  g_xlo [(size_t)BT_ * IN_];
__device__ __nv_bfloat16 g_a1hi[(size_t)BT_ * W1_],  g_a1lo[(size_t)BT_ * W1_];
__device__ __nv_bfloat16 g_a2hi[(size_t)BT_ * W2_],  g_a2lo[(size_t)BT_ * W2_];
__device__ __nv_bfloat16 g_w1Thi[W1_ * IN_], g_w1Tlo[W1_ * IN_];  // also att_w (256*256)
__device__ __nv_bfloat16 g_w2Thi[W2_ * W1_], g_w2Tlo[W2_ * W1_];
__device__ __nv_bfloat16 g_w3Thi[H_  * W2_], g_w3Tlo[H_  * W2_];

// ---------------------------------------------------------------------------
// helpers
// ---------------------------------------------------------------------------
typedef unsigned long long u64;

__device__ __forceinline__ u64 fma2(u64 a, u64 b, u64 c) {
    u64 d;
    asm("fma.rn.f32x2 %0, %1, %2, %3;" : "=l"(d) : "l"(a), "l"(b), "l"(c));
    return d;
}
__device__ __forceinline__ u64 dup2(float x) {
    u64 d; unsigned int u = __float_as_uint(x);
    asm("mov.b64 %0, {%1, %1};" : "=l"(d) : "r"(u));
    return d;
}
__device__ __forceinline__ void unpack2(u64 v, float& lo, float& hi) {
    unsigned int a, b;
    asm("mov.b64 {%0, %1}, %2;" : "=r"(a), "=r"(b) : "l"(v));
    lo = __uint_as_float(a); hi = __uint_as_float(b);
}
__device__ __forceinline__ uint32_t smem_u32(const void* p) {
    uint32_t a;
    asm("{ .reg .u64 t; cvta.to.shared.u64 t, %1; cvt.u32.u64 %0, t; }"
        : "=r"(a) : "l"(p));
    return a;
}
__device__ __forceinline__ void mbar_init(uint32_t mbar, uint32_t count) {
    asm volatile("mbarrier.init.shared.b64 [%0], %1;" :: "r"(mbar), "r"(count) : "memory");
}
__device__ __forceinline__ void mbar_expect_tx(uint32_t mbar, uint32_t bytes) {
    asm volatile("mbarrier.arrive.expect_tx.shared.b64 _, [%0], %1;"
                 :: "r"(mbar), "r"(bytes) : "memory");
}
__device__ __forceinline__ void mbar_wait_parity(uint32_t mbar, uint32_t parity) {
    asm volatile(
        "{\n\t"
        ".reg .pred P;\n\t"
        "WAIT_%=:\n\t"
        "mbarrier.try_wait.parity.shared.b64 P, [%0], %1, 0x989680;\n\t"
        "@P bra.uni DONE_%=;\n\t"
        "bra.uni WAIT_%=;\n\t"
        "DONE_%=:\n\t"
        "}"
        :: "r"(mbar), "r"(parity) : "memory");
}
__device__ __forceinline__ uint32_t mapa_rank(uint32_t addr, uint32_t rank) {
    uint32_t r;
    asm("mapa.shared::cluster.u32 %0, %1, %2;" : "=r"(r) : "r"(addr), "r"(rank));
    return r;
}
__device__ __forceinline__ void mbar_arrive_remote(uint32_t cluster_addr) {
    asm volatile("mbarrier.arrive.shared::cluster.b64 _, [%0];"
                 :: "r"(cluster_addr) : "memory");
}
__device__ __forceinline__ void bulk_g2s_mc(uint32_t dst_smem, const void* src_gmem,
                                            uint32_t bytes, uint32_t mbar, uint16_t mask) {
    asm volatile(
        "cp.async.bulk.shared::cluster.global.mbarrier::complete_tx::bytes.multicast::cluster "
        "[%0], [%1], %2, [%3], %4;"
        :: "r"(dst_smem), "l"(src_gmem), "r"(bytes), "r"(mbar), "h"(mask) : "memory");
}
__device__ __forceinline__ uint32_t cluster_rank() {
    uint32_t r; asm("mov.u32 %0, %%cluster_ctarank;" : "=r"(r)); return r;
}
#define CLUSTER_SYNC() do { \
    asm volatile("barrier.cluster.arrive.aligned;" ::: "memory"); \
    asm volatile("barrier.cluster.wait.aligned;"   ::: "memory"); \
} while (0)

__device__ __forceinline__ void cp16(uint32_t dst, const void* src) {
    asm volatile("cp.async.cg.shared.global [%0], [%1], 16;" :: "r"(dst), "l"(src));
}

// ---------------------------------------------------------------------------
// bf16 hi/lo split helpers + kernels
// ---------------------------------------------------------------------------
__device__ __forceinline__ void split_bf16(float v, __nv_bfloat16& h, __nv_bfloat16& l) {
    h = __float2bfloat16(v);
    l = __float2bfloat16(v - __bfloat162float(h));
}

__global__ void split_kernel(const float* __restrict__ in, __nv_bfloat16* __restrict__ hi,
                             __nv_bfloat16* __restrict__ lo, int n)
{
    int i = (blockIdx.x * 256 + threadIdx.x) * 4;
    if (i >= n) return;
    float4 v = *(const float4*)(in + i);
    __nv_bfloat16 h0, l0, h1, l1, h2, l2, h3, l3;
    split_bf16(v.x, h0, l0); split_bf16(v.y, h1, l1);
    split_bf16(v.z, h2, l2); split_bf16(v.w, h3, l3);
    __nv_bfloat162 hp0 = {h0, h1}, hp1 = {h2, h3}, lp0 = {l0, l1}, lp1 = {l2, l3};
    *(uint2*)(hi + i) = make_uint2(*(uint32_t*)&hp0, *(uint32_t*)&hp1);
    *(uint2*)(lo + i) = make_uint2(*(uint32_t*)&lp0, *(uint32_t*)&lp1);
}

// in: [Kd, Nd] row-major -> out transposed [Nd, Kd] hi/lo bf16
__global__ void splitT_kernel(const float* __restrict__ in, __nv_bfloat16* __restrict__ hiT,
                              __nv_bfloat16* __restrict__ loT, int Kd, int Nd)
{
    int idx = blockIdx.x * 256 + threadIdx.x;
    if (idx >= Kd * Nd) return;
    int k = idx / Nd, n2 = idx - k * Nd;
    __nv_bfloat16 h, l;
    split_bf16(in[idx], h, l);
    hiT[(size_t)n2 * Kd + k] = h;
    loT[(size_t)n2 * Kd + k] = l;
}

// ---------------------------------------------------------------------------
// bf16-split GEMM via mma.sync (m16n8k16) with 2-stage cp.async pipeline.
//   D[M,N] = act(A @ W + bias);  A as (Ahi,Alo)[M,K] K-major,
//   W as (Bhi,Blo)[N,K] (transposed).  D = Ahi*Bhi^T + Ahi*Blo^T + Alo*Bhi^T.
// CTA tile 128x128, BK=32, 8 warps as 2(M)x4(N).
// ACT: 0 none, 1 relu, 2 tanh.
// OUT: 0 = fp32 direct, 1 = fp32 PERM (row b*T+t -> t*B+b), 2 = bf16 hi/lo.
// ---------------------------------------------------------------------------
#define PADK 40                            // bf16 per smem row: 80B, 16B-aligned
#define ROWB (PADK * 2)                    // 80
#define TILE_B (128 * ROWB)                // 10240
#define STAGE_B (4 * TILE_B)               // 40960
#define MMA_SMEM (2 * STAGE_B)             // 81920

template <int ACT, int OUT>
__global__ void __launch_bounds__(256)
mm_mma_kernel(const __nv_bfloat16* __restrict__ Ahi, const __nv_bfloat16* __restrict__ Alo,
              const __nv_bfloat16* __restrict__ Bhi, const __nv_bfloat16* __restrict__ Blo,
              const float* __restrict__ bias,
              __nv_bfloat16* __restrict__ Chi, __nv_bfloat16* __restrict__ Clo,
              float* __restrict__ Cf, int M, int N, int K)
{
    extern __shared__ char dsm[];
    const uint32_t sb = smem_u32(dsm);

    const int tid = threadIdx.x, lane = tid & 31, wid = tid >> 5;
    const int wm = wid >> 2, wn = wid & 3;
    const int bn = blockIdx.x, bm = blockIdx.y;

    float acc[4][4][4];
#pragma unroll
    for (int i = 0; i < 4; i++)
#pragma unroll
        for (int j = 0; j < 4; j++)
#pragma unroll
            for (int q = 0; q < 4; q++) acc[i][j][q] = 0.f;

    const __nv_bfloat16* srcs[4] = {
        Ahi + (size_t)(bm * 128) * K, Alo + (size_t)(bm * 128) * K,
        Bhi + (size_t)(bn * 128) * K, Blo + (size_t)(bn * 128) * K };

    const int frow = lane >> 2;
    const int fcol = (lane & 3) * 2;

    int stage = 0;
    // prologue: load stage 0 (k0 = 0)
#pragma unroll
    for (int it = 0; it < 8; it++) {
        const int id = tid + it * 256;
        const int tile = id >> 9, rem = id & 511, row = rem >> 2, ch = rem & 3;
        cp16(sb + tile * TILE_B + row * ROWB + ch * 16,
             srcs[tile] + (size_t)row * K + ch * 8);
    }
    asm volatile("cp.async.commit_group;" ::: "memory");

    for (int k0 = 0; k0 < K; k0 += 32) {
        if (k0 + 32 < K) {
            const int nb = (stage ^ 1) * STAGE_B;
#pragma unroll
            for (int it = 0; it < 8; it++) {
                const int id = tid + it * 256;
                const int tile = id >> 9, rem = id & 511, row = rem >> 2, ch = rem & 3;
                cp16(sb + nb + tile * TILE_B + row * ROWB + ch * 16,
                     srcs[tile] + (size_t)row * K + k0 + 32 + ch * 8);
            }
            asm volatile("cp.async.commit_group;" ::: "memory");
            asm volatile("cp.async.wait_group 1;" ::: "memory");
        } else {
            asm volatile("cp.async.wait_group 0;" ::: "memory");
        }
        __syncthreads();

        const __nv_bfloat16* sAh = (const __nv_bfloat16*)(dsm + stage * STAGE_B);
        const __nv_bfloat16* sAl = sAh + 128 * PADK;
        const __nv_bfloat16* sBh = sAl + 128 * PADK;
        const __nv_bfloat16* sBl = sBh + 128 * PADK;

#pragma unroll
        for (int ks = 0; ks < 2; ks++) {
            const int kb = ks * 16 + fcol;
            uint32_t Afh[4][4], Afl[4][4], Bfh[4][2], Bfl[4][2];
#pragma unroll
            for (int mt = 0; mt < 4; mt++) {
                const int r0 = (wm * 64 + mt * 16 + frow) * PADK + kb;
                const int r1 = r0 + 8 * PADK;
                Afh[mt][0] = *(const uint32_t*)(sAh + r0);
                Afh[mt][1] = *(const uint32_t*)(sAh + r1);
                Afh[mt][2] = *(const uint32_t*)(sAh + r0 + 8);
                Afh[mt][3] = *(const uint32_t*)(sAh + r1 + 8);
                Afl[mt][0] = *(const uint32_t*)(sAl + r0);
                Afl[mt][1] = *(const uint32_t*)(sAl + r1);
                Afl[mt][2] = *(const uint32_t*)(sAl + r0 + 8);
                Afl[mt][3] = *(const uint32_t*)(sAl + r1 + 8);
            }
#pragma unroll
            for (int nt = 0; nt < 4; nt++) {
                const int n0 = (wn * 32 + nt * 8 + frow) * PADK + kb;
                Bfh[nt][0] = *(const uint32_t*)(sBh + n0);
                Bfh[nt][1] = *(const uint32_t*)(sBh + n0 + 8);
                Bfl[nt][0] = *(const uint32_t*)(sBl + n0);
                Bfl[nt][1] = *(const uint32_t*)(sBl + n0 + 8);
            }
#pragma unroll
            for (int mt = 0; mt < 4; mt++)
#pragma unroll
                for (int nt = 0; nt < 4; nt++) {
                    float* d = acc[mt][nt];
                    asm volatile(
                        "mma.sync.aligned.m16n8k16.row.col.f32.bf16.bf16.f32 "
                        "{%0,%1,%2,%3}, {%4,%5,%6,%7}, {%8,%9}, {%0,%1,%2,%3};"
                        : "+f"(d[0]), "+f"(d[1]), "+f"(d[2]), "+f"(d[3])
                        : "r"(Afh[mt][0]), "r"(Afh[mt][1]), "r"(Afh[mt][2]), "r"(Afh[mt][3]),
                          "r"(Bfh[nt][0]), "r"(Bfh[nt][1]));
                    asm volatile(
                        "mma.sync.aligned.m16n8k16.row.col.f32.bf16.bf16.f32 "
                        "{%0,%1,%2,%3}, {%4,%5,%6,%7}, {%8,%9}, {%0,%1,%2,%3};"
                        : "+f"(d[0]), "+f"(d[1]), "+f"(d[2]), "+f"(d[3])
                        : "r"(Afh[mt][0]), "r"(Afh[mt][1]), "r"(Afh[mt][2]), "r"(Afh[mt][3]),
                          "r"(Bfl[nt][0]), "r"(Bfl[nt][1]));
                    asm volatile(
                        "mma.sync.aligned.m16n8k16.row.col.f32.bf16.bf16.f32 "
                        "{%0,%1,%2,%3}, {%4,%5,%6,%7}, {%8,%9}, {%0,%1,%2,%3};"
                        : "+f"(d[0]), "+f"(d[1]), "+f"(d[2]), "+f"(d[3])
                        : "r"(Afl[mt][0]), "r"(Afl[mt][1]), "r"(Afl[mt][2]), "r"(Afl[mt][3]),
                          "r"(Bfh[nt][0]), "r"(Bfh[nt][1]));
                }
        }
        __syncthreads();
        stage ^= 1;
    }

    // Epilogue: lane holds rows (r, r+8), cols (c, c+1) per frag
#pragma unroll
    for (int mt = 0; mt < 4; mt++) {
        const int rA = bm * 128 + wm * 64 + mt * 16 + frow;
        const int rB = rA + 8;
#pragma unroll
        for (int nt = 0; nt < 4; nt++) {
            const int c = bn * 128 + wn * 32 + nt * 8 + fcol;
            float v00 = acc[mt][nt][0] + bias[c];
            float v01 = acc[mt][nt][1] + bias[c + 1];
            float v10 = acc[mt][nt][2] + bias[c];
            float v11 = acc[mt][nt][3] + bias[c + 1];
            if (ACT == 1) {
                v00 = fmaxf(v00, 0.f); v01 = fmaxf(v01, 0.f);
                v10 = fmaxf(v10, 0.f); v11 = fmaxf(v11, 0.f);
            } else if (ACT == 2) {
                v00 = tanhf(v00); v01 = tanhf(v01);
                v10 = tanhf(v10); v11 = tanhf(v11);
            }
            if (OUT == 2) {
                __nv_bfloat16 h0, l0, h1, l1;
                split_bf16(v00, h0, l0); split_bf16(v01, h1, l1);
                uint32_t hp = (uint32_t)__bfloat16_as_ushort(h0) |
                              ((uint32_t)__bfloat16_as_ushort(h1) << 16);
                uint32_t lp = (uint32_t)__bfloat16_as_ushort(l0) |
                              ((uint32_t)__bfloat16_as_ushort(l1) << 16);
                *(uint32_t*)(Chi + (size_t)rA * N + c) = hp;
                *(uint32_t*)(Clo + (size_t)rA * N + c) = lp;
                split_bf16(v10, h0, l0); split_bf16(v11, h1, l1);
                hp = (uint32_t)__bfloat16_as_ushort(h0) |
                     ((uint32_t)__bfloat16_as_ushort(h1) << 16);
                lp = (uint32_t)__bfloat16_as_ushort(l0) |
                     ((uint32_t)__bfloat16_as_ushort(l1) << 16);
                *(uint32_t*)(Chi + (size_t)rB * N + c) = hp;
                *(uint32_t*)(Clo + (size_t)rB * N + c) = lp;
            } else if (OUT == 1) {
                const int bA = rA >> 9, tA = rA & (T_ - 1);
                const int bB = rB >> 9, tB = rB & (T_ - 1);
                *(float2*)(Cf + (size_t)(tA * B_ + bA) * N + c) = make_float2(v00, v01);
                *(float2*)(Cf + (size_t)(tB * B_ + bB) * N + c) = make_float2(v10, v11);
            } else {
                *(float2*)(Cf + (size_t)rA * N + c) = make_float2(v00, v01);
                *(float2*)(Cf + (size_t)rB * N + c) = make_float2(v10, v11);
            }
        }
    }
}

// ---------------------------------------------------------------------------
// Phase B: persistent recurrence (verified Round 10 config — UNCHANGED).
// ---------------------------------------------------------------------------
#define NSTAGE      4
#define CHUNK_F     8192
#define CHUNK_BYTES (CHUNK_F * 4)
#define CHUNKS_PER_STEP 64
#define TOTAL_CHUNKS    (T_ * CHUNKS_PER_STEP)
#define MC_MASK     0xFu

#define SM_WBUF  0
#define SM_HT    (NSTAGE * CHUNK_F)
#define SM_Y1T   (SM_HT + H_ * 2)
#define SM_Y2T   (SM_Y1T + W1_ * 2)
#define SM_B1    (SM_Y2T + W2_ * 2)
#define SM_B2    (SM_B1 + W1_)
#define SM_B3    (SM_B2 + W2_)
#define SM_FULL  (SM_B3 + H_)
#define SM_EMPTY (SM_FULL + 2 * NSTAGE)
#define SMEM_FLOATS (SM_EMPTY + 2 * NSTAGE)
#define SMEM_BYTES  (SMEM_FLOATS * 4)

struct WSrc { const float* w1; const float* w2; const float* w3; };

__device__ __forceinline__ const float* chunk_src(const WSrc& w, int cg) {
    int c = cg & (CHUNKS_PER_STEP - 1);
    if (c < 16)      return w.w1 + (size_t)c * 16 * W1_;
    else if (c < 48) return w.w2 + (size_t)(c - 16) * 16 * W2_;
    else             return w.w3 + (size_t)(c - 48) * 32 * H_;
}

__global__ void __launch_bounds__(256, 1) __cluster_dims__(4, 1, 1)
recurrence_kernel(const float* __restrict__ w1, const float* __restrict__ b1,
                  const float* __restrict__ w2, const float* __restrict__ b2,
                  const float* __restrict__ w3, const float* __restrict__ b3,
                  const float* __restrict__ xin, float* __restrict__ hs)
{
    extern __shared__ float smemf[];
    float* wbuf = smemf + SM_WBUF;
    float* hT   = smemf + SM_HT;
    float* y1T  = smemf + SM_Y1T;
    float* y2T  = smemf + SM_Y2T;
    float* bs1  = smemf + SM_B1;
    float* bs2  = smemf + SM_B2;
    float* bs3  = smemf + SM_B3;
    const uint32_t fullb  = smem_u32(smemf + SM_FULL);
    const uint32_t emptyb = smem_u32(smemf + SM_EMPTY);

    const int tid = threadIdx.x;
    const int b0  = blockIdx.x * 2;
    const uint32_t rank = cluster_rank();
    WSrc wsrc = { w1, w2, w3 };

    for (int i = tid; i < W1_; i += 256) bs1[i] = b1[i];
    for (int i = tid; i < W2_; i += 256) bs2[i] = b2[i];
    for (int i = tid; i < H_;  i += 256) bs3[i] = b3[i];
    for (int i = tid; i < H_ * 2; i += 256) hT[i] = 0.f;
    if (tid == 0) {
#pragma unroll
        for (int s = 0; s < NSTAGE; s++) {
            mbar_init(fullb  + s * 8, 1);
            mbar_init(emptyb + s * 8, NSTAGE);
        }
    }
    __syncthreads();

    if (tid == 0) {
#pragma unroll
        for (int s = 0; s < NSTAGE; s++) mbar_expect_tx(fullb + s * 8, CHUNK_BYTES);
    }
    CLUSTER_SYNC();
    if (tid == 0) {
        bulk_g2s_mc(smem_u32(wbuf + rank * CHUNK_F), chunk_src(wsrc, (int)rank),
                    CHUNK_BYTES, fullb + rank * 8, MC_MASK);
    }

    int chunk = 0;

#define PAIR_BOOKKEEP()                                                         \
    do {                                                                        \
        __syncthreads();                                                        \
        if (tid == 0) {                                                         \
            _Pragma("unroll")                                                   \
            for (int q = 0; q < 2; q++) {                                       \
                const int cq = chunk + q;                                       \
                if (cq + NSTAGE < TOTAL_CHUNKS) {                               \
                    const int s_ = cq & (NSTAGE - 1);                           \
                    mbar_expect_tx(fullb + s_ * 8, CHUNK_BYTES);                \
                    mbar_arrive_remote(mapa_rank(emptyb + s_ * 8, (uint32_t)s_));\
                    if (rank == (uint32_t)s_) {                                 \
                        mbar_wait_parity(emptyb + s_ * 8, (cq >> 2) & 1);       \
                        bulk_g2s_mc(smem_u32(wbuf + s_ * CHUNK_F),              \
                                    chunk_src(wsrc, cq + NSTAGE),               \
                                    CHUNK_BYTES, fullb + s_ * 8, MC_MASK);      \
                    }                                                           \
                }                                                               \
            }                                                                   \
        }                                                                       \
        chunk += 2;                                                             \
    } while (0)

    for (int t = 0; t < T_; t++) {
        const int c0 = tid * 2;

        {   // Layer 1: K=256, 8 pairs
            u64 a0 = 0, a1 = 0;
            for (int jp = 0; jp < 8; jp++) {
                const int s0 = chunk & (NSTAGE - 1);
                const int s1 = (chunk + 1) & (NSTAGE - 1);
                mbar_wait_parity(fullb + s0 * 8, (chunk >> 2) & 1);
                mbar_wait_parity(fullb + s1 * 8, ((chunk + 1) >> 2) & 1);
                const float* wb0 = wbuf + s0 * CHUNK_F;
                const float* wb1 = wbuf + s1 * CHUNK_F;
#pragma unroll
                for (int kk = 0; kk < 16; kk++) {
                    const int k = jp * 32 + kk;
                    u64 r = *(const u64*)(hT + k * 2);
                    float2 w = *(const float2*)(wb0 + kk * W1_ + c0);
                    a0 = fma2(r, dup2(w.x), a0);
                    a1 = fma2(r, dup2(w.y), a1);
                }
#pragma unroll
                for (int kk = 0; kk < 16; kk++) {
                    const int k = jp * 32 + 16 + kk;
                    u64 r = *(const u64*)(hT + k * 2);
                    float2 w = *(const float2*)(wb1 + kk * W1_ + c0);
                    a0 = fma2(r, dup2(w.x), a0);
                    a1 = fma2(r, dup2(w.y), a1);
                }
                PAIR_BOOKKEEP();
            }
            float v0, v1;
            const float bb0 = bs1[c0], bb1 = bs1[c0 + 1];
            unpack2(a0, v0, v1);
            *(float2*)(y1T + c0 * 2) =
                make_float2(fmaxf(v0 + bb0, 0.f), fmaxf(v1 + bb0, 0.f));
            unpack2(a1, v0, v1);
            *(float2*)(y1T + (c0 + 1) * 2) =
                make_float2(fmaxf(v0 + bb1, 0.f), fmaxf(v1 + bb1, 0.f));
        }
        __syncthreads();

        {   // Layer 2: K=512, 16 pairs
            u64 a0 = 0, a1 = 0;
            for (int jp = 0; jp < 16; jp++) {
                const int s0 = chunk & (NSTAGE - 1);
                const int s1 = (chunk + 1) & (NSTAGE - 1);
                mbar_wait_parity(fullb + s0 * 8, (chunk >> 2) & 1);
                mbar_wait_parity(fullb + s1 * 8, ((chunk + 1) >> 2) & 1);
                const float* wb0 = wbuf + s0 * CHUNK_F;
                const float* wb1 = wbuf + s1 * CHUNK_F;
#pragma unroll
                for (int kk = 0; kk < 16; kk++) {
                    const int k = jp * 32 + kk;
                    u64 r = *(const u64*)(y1T + k * 2);
                    float2 w = *(const float2*)(wb0 + kk * W2_ + c0);
                    a0 = fma2(r, dup2(w.x), a0);
                    a1 = fma2(r, dup2(w.y), a1);
                }
#pragma unroll
                for (int kk = 0; kk < 16; kk++) {
                    const int k = jp * 32 + 16 + kk;
                    u64 r = *(const u64*)(y1T + k * 2);
                    float2 w = *(const float2*)(wb1 + kk * W2_ + c0);
                    a0 = fma2(r, dup2(w.x), a0);
                    a1 = fma2(r, dup2(w.y), a1);
                }
                PAIR_BOOKKEEP();
            }
            float v0, v1;
            const float bb0 = bs2[c0], bb1 = bs2[c0 + 1];
            unpack2(a0, v0, v1);
            *(float2*)(y2T + c0 * 2) =
                make_float2(fmaxf(v0 + bb0, 0.f), fmaxf(v1 + bb0, 0.f));
            unpack2(a1, v0, v1);
            *(float2*)(y2T + (c0 + 1) * 2) =
                make_float2(fmaxf(v0 + bb1, 0.f), fmaxf(v1 + bb1, 0.f));
        }
        __syncthreads();

        {   // Layer 3: K=512, 8 pairs (64 k per pair)
            const int c = tid;
            u64 ae = 0, ao = 0;
            for (int jp = 0; jp < 8; jp++) {
                const int s0 = chunk & (NSTAGE - 1);
                const int s1 = (chunk + 1) & (NSTAGE - 1);
                mbar_wait_parity(fullb + s0 * 8, (chunk >> 2) & 1);
                mbar_wait_parity(fullb + s1 * 8, ((chunk + 1) >> 2) & 1);
                const float* wb0 = wbuf + s0 * CHUNK_F;
                const float* wb1 = wbuf + s1 * CHUNK_F;
#pragma unroll
                for (int kk = 0; kk < 32; kk += 2) {
                    const int k = jp * 64 + kk;
                    u64 r0 = *(const u64*)(y2T + k * 2);
                    u64 r1 = *(const u64*)(y2T + (k + 1) * 2);
                    ae = fma2(r0, dup2(wb0[kk * H_ + c]),       ae);
                    ao = fma2(r1, dup2(wb0[(kk + 1) * H_ + c]), ao);
                }
#pragma unroll
                for (int kk = 0; kk < 32; kk += 2) {
                    const int k = jp * 64 + 32 + kk;
                    u64 r0 = *(const u64*)(y2T + k * 2);
                    u64 r1 = *(const u64*)(y2T + (k + 1) * 2);
                    ae = fma2(r0, dup2(wb1[kk * H_ + c]),       ae);
                    ao = fma2(r1, dup2(wb1[(kk + 1) * H_ + c]), ao);
                }
                PAIR_BOOKKEEP();
            }
            float e0, e1, o0, o1;
            unpack2(ae, e0, e1); unpack2(ao, o0, o1);
            const float bb = bs3[c];
            const float* xr = xin + (size_t)t * B_ * H_ + (size_t)b0 * H_ + c;
            float*       hr = hs  + (size_t)t * B_ * H_ + (size_t)b0 * H_ + c;
            float v0 = tanhf(e0 + o0 + bb + xr[0 * H_]);
            float v1 = tanhf(e1 + o1 + bb + xr[1 * H_]);
            hr[0 * H_] = v0; hr[1 * H_] = v1;
            *(float2*)(hT + c * 2) = make_float2(v0, v1);
        }
        __syncthreads();
    }

    CLUSTER_SYNC();
#undef PAIR_BOOKKEEP
}

// ---------------------------------------------------------------------------
// Phase C reduction: online softmax over T (axis 0) + weighted sum of hs.
// ---------------------------------------------------------------------------
__global__ void attn_reduce_kernel(const float* __restrict__ aw,
                                   const float* __restrict__ hs,
                                   float* __restrict__ out)
{
    const int b = blockIdx.x;
    const int h = threadIdx.x;
    float m = -1e30f, s = 0.f, acc = 0.f;
    for (int t = 0; t < T_; t++) {
        size_t idx = ((size_t)t * B_ + b) * H_ + h;
        float a  = aw[idx];
        float hv = hs[idx];
        if (a > m) {
            float c = __expf(m - a);
            s   = s * c + 1.f;
            acc = acc * c + hv;
            m   = a;
        } else {
            float e = __expf(a - m);
            s   += e;
            acc += e * hv;
        }
    }
    out[(size_t)b * H_ + h] = acc / s;
}

// ---------------------------------------------------------------------------
// Launch
// ---------------------------------------------------------------------------
extern "C" void kernel_launch(void* const* d_in, const int* in_sizes, int n_in,
                              void* d_out, int out_size)
{
    const float* x     = (const float*)d_in[0];
    const float* h_w1  = (const float*)d_in[1];
    const float* h_b1  = (const float*)d_in[2];
    const float* h_w2  = (const float*)d_in[3];
    const float* h_b2  = (const float*)d_in[4];
    const float* h_w3  = (const float*)d_in[5];
    const float* h_b3  = (const float*)d_in[6];
    const float* i_w1  = (const float*)d_in[7];
    const float* i_b1  = (const float*)d_in[8];
    const float* i_w2  = (const float*)d_in[9];
    const float* i_b2  = (const float*)d_in[10];
    const float* i_w3  = (const float*)d_in[11];
    const float* i_b3  = (const float*)d_in[12];
    const float* att_w = (const float*)d_in[13];
    const float* att_b = (const float*)d_in[14];
    float* out = (float*)d_out;

    float *aw, *xin, *hs;
    cudaGetSymbolAddress((void**)&aw,  g_aw);
    cudaGetSymbolAddress((void**)&xin, g_xin);
    cudaGetSymbolAddress((void**)&hs,  g_hs);
    __nv_bfloat16 *xhi, *xlo, *a1hi, *a1lo, *a2hi, *a2lo;
    __nv_bfloat16 *w1Thi, *w1Tlo, *w2Thi, *w2Tlo, *w3Thi, *w3Tlo;
    cudaGetSymbolAddress((void**)&xhi,  g_xhi);  cudaGetSymbolAddress((void**)&xlo,  g_xlo);
    cudaGetSymbolAddress((void**)&a1hi, g_a1hi); cudaGetSymbolAddress((void**)&a1lo, g_a1lo);
    cudaGetSymbolAddress((void**)&a2hi, g_a2hi); cudaGetSymbolAddress((void**)&a2lo, g_a2lo);
    cudaGetSymbolAddress((void**)&w1Thi, g_w1Thi); cudaGetSymbolAddress((void**)&w1Tlo, g_w1Tlo);
    cudaGetSymbolAddress((void**)&w2Thi, g_w2Thi); cudaGetSymbolAddress((void**)&w2Tlo, g_w2Tlo);
    cudaGetSymbolAddress((void**)&w3Thi, g_w3Thi); cudaGetSymbolAddress((void**)&w3Tlo, g_w3Tlo);

    cudaFuncSetAttribute(mm_mma_kernel<1, 2>,
                         cudaFuncAttributeMaxDynamicSharedMemorySize, MMA_SMEM);
    cudaFuncSetAttribute(mm_mma_kernel<0, 1>,
                         cudaFuncAttributeMaxDynamicSharedMemorySize, MMA_SMEM);
    cudaFuncSetAttribute(mm_mma_kernel<2, 0>,
                         cudaFuncAttributeMaxDynamicSharedMemorySize, MMA_SMEM);

    // ---------------- Phase A: bf16-split mma.sync input MLP --------------
    split_kernel<<<(BT_ * IN_) / 1024, 256>>>(x, xhi, xlo, BT_ * IN_);
    splitT_kernel<<<(IN_ * W1_) / 256, 256>>>(i_w1, w1Thi, w1Tlo, IN_, W1_);
    splitT_kernel<<<(W1_ * W2_) / 256, 256>>>(i_w2, w2Thi, w2Tlo, W1_, W2_);
    splitT_kernel<<<(W2_ * H_)  / 256, 256>>>(i_w3, w3Thi, w3Tlo, W2_, H_);

    mm_mma_kernel<1, 2><<<dim3(W1_ / 128, BT_ / 128), 256, MMA_SMEM>>>(
        xhi, xlo, w1Thi, w1Tlo, i_b1, a1hi, a1lo, nullptr, BT_, W1_, IN_);
    mm_mma_kernel<1, 2><<<dim3(W2_ / 128, BT_ / 128), 256, MMA_SMEM>>>(
        a1hi, a1lo, w2Thi, w2Tlo, i_b2, a2hi, a2lo, nullptr, BT_, W2_, W1_);
    mm_mma_kernel<0, 1><<<dim3(H_ / 128, BT_ / 128), 256, MMA_SMEM>>>(
        a2hi, a2lo, w3Thi, w3Tlo, i_b3, nullptr, nullptr, xin, BT_, H_, W2_);

    // ---------------- Phase B: persistent recurrence (ONE launch) ---------
    cudaFuncSetAttribute(recurrence_kernel,
                         cudaFuncAttributeMaxDynamicSharedMemorySize, SMEM_BYTES);
    recurrence_kernel<<<128, 256, SMEM_BYTES>>>(
        h_w1, h_b1, h_w2, h_b2, h_w3, h_b3, xin, hs);

    // ---------------- Phase C: attention pooling (tensor path) ------------
    // split hs -> a2hi/a2lo (reused), att_w^T -> w1Thi/w1Tlo (256*256 fits)
    split_kernel<<<(BT_ * H_) / 1024, 256>>>(hs, a2hi, a2lo, BT_ * H_);
    splitT_kernel<<<(H_ * H_) / 256, 256>>>(att_w, w1Thi, w1Tlo, H_, H_);
    mm_mma_kernel<2, 0><<<dim3(H_ / 128, BT_ / 128), 256, MMA_SMEM>>>(
        a2hi, a2lo, w1Thi, w1Tlo, att_b, nullptr, nullptr, aw, BT_, H_, H_);
    attn_reduce_kernel<<<B_, H_>>>(aw, hs, out);
}